// round 10
// baseline (speedup 1.0000x reference)
#include <cuda_runtime.h>
#include <math.h>
#include <stdint.h>

#define Bn 16
#define Cn 64
#define Hn 128
#define Wn 128
#define MXn 24
#define MYn 24
#define HIDn 32

// ---------------- scratch (device globals; no runtime allocation) ----------
__device__ float g_xft_re[MXn*MYn*Bn*Cn];     // [(kx*24+ky)][b][c]
__device__ float g_xft_im[MXn*MYn*Bn*Cn];
__device__ float g_oftI[Bn*MXn*MYn*Cn*2];     // [b][m][o][re,im]
__device__ float g_cos[MYn*Wn];               // cos(2*pi*k*p/128)
__device__ float g_sin[MYn*Wn];               // sin(2*pi*k*p/128)
__device__ float g_twT[Wn*48];                // [w][j] j<24: cos, j>=24: -sin

// ---------------- packed f32x2 helpers ----------------
__device__ __forceinline__ float2 ffma2(float2 a, float2 b, float2 c) {
    float2 r;
    asm("fma.rn.f32x2 %0, %1, %2, %3;"
        : "=l"(reinterpret_cast<unsigned long long&>(r))
        : "l"(reinterpret_cast<unsigned long long&>(a)),
          "l"(reinterpret_cast<unsigned long long&>(b)),
          "l"(reinterpret_cast<unsigned long long&>(c)));
    return r;
}
__device__ __forceinline__ float2 dup2(float x) { return make_float2(x, x); }

__device__ __forceinline__ float gelu_f(float v) {
    return 0.5f*v*(1.0f + erff(v*0.7071067811865476f));
}

// ---------------- K0: twiddle init ----------------
__global__ void k0_init() {
    int i = blockIdx.x*blockDim.x + threadIdx.x;
    if (i >= MYn*Wn) return;
    int k = i / Wn, w = i % Wn;
    float s, c;
    sincospif((float)(k*w) / 64.0f, &s, &c);
    g_cos[k*Wn + w] = c;
    g_sin[k*Wn + w] = s;
    g_twT[w*48 + k]      = c;
    g_twT[w*48 + 24 + k] = -s;
}

// ---------------- kA: fused partial DFT over W then H, per (b,c) ----------
#define KA_SMEM_FLOATS 18112

__global__ void __launch_bounds__(384) kA_dft(const float* __restrict__ x) {
    extern __shared__ float sma[];
    float* Xs  = sma;            // 4224
    float* Tw  = sma + 4224;     // 1536
    float* xwr = sma + 5760;     // 3104
    float* xwi = sma + 8864;     // 3104
    float* cs  = sma + 11968;    // 3072
    float* sn  = sma + 15040;    // 3072

    int tid = threadIdx.x;
    int rg = tid & 31;
    int jg = tid >> 5;
    int row0 = blockIdx.x * 128;

    for (int i = tid; i < 3072; i += 384) { cs[i] = g_cos[i]; sn[i] = g_sin[i]; }

    float2 acc[2][4];
    #pragma unroll
    for (int i = 0; i < 2; i++)
        #pragma unroll
        for (int j = 0; j < 4; j++) acc[i][j] = make_float2(0.f, 0.f);

    for (int kt = 0; kt < 4; kt++) {
        for (int i = tid; i < 4096; i += 384) {
            int r = i >> 5, w = i & 31;
            Xs[w*132 + r] = x[(size_t)(row0 + r)*128 + kt*32 + w];
        }
        for (int i = tid; i < 32*48; i += 384)
            Tw[i] = g_twT[kt*32*48 + i];
        __syncthreads();
        #pragma unroll
        for (int kk = 0; kk < 32; kk++) {
            float4 xa = *(const float4*)&Xs[kk*132 + 4*rg];
            float2 xp0 = make_float2(xa.x, xa.y);
            float2 xp1 = make_float2(xa.z, xa.w);
            float4 tq = *(const float4*)&Tw[kk*48 + 4*jg];
            float tv[4] = { tq.x, tq.y, tq.z, tq.w };
            #pragma unroll
            for (int j = 0; j < 4; j++) {
                float2 td = dup2(tv[j]);
                acc[0][j] = ffma2(xp0, td, acc[0][j]);
                acc[1][j] = ffma2(xp1, td, acc[1][j]);
            }
        }
        __syncthreads();
    }

    {
        float* dst = (jg < 6) ? xwr : xwi;
        int colbase = (jg < 6) ? (4*jg) : (4*jg - 24);
        #pragma unroll
        for (int i = 0; i < 4; i++) {
            int pair = i >> 1, half = i & 1;
            int h = 4*rg + i;
            #pragma unroll
            for (int j = 0; j < 4; j++) {
                float v = half ? acc[pair][j].y : acc[pair][j].x;
                dst[(colbase + j)*129 + h] = v;
            }
        }
    }
    __syncthreads();

    if (tid < 288) {
        int ky  = tid % 24;
        int kxg = tid / 24;
        int kx0 = 2*kxg, kx1 = 2*kxg + 1;
        float2 acc0 = make_float2(0.f, 0.f);
        float2 acc1 = make_float2(0.f, 0.f);
        #pragma unroll 4
        for (int h = 0; h < 128; h++) {
            float a = xwr[ky*129 + h];
            float b = xwi[ky*129 + h];
            float2 ab  = make_float2(a, b);
            float2 bna = make_float2(b, -a);
            acc0 = ffma2(ab,  dup2(cs[kx0*128 + h]), acc0);
            acc0 = ffma2(bna, dup2(sn[kx0*128 + h]), acc0);
            acc1 = ffma2(ab,  dup2(cs[kx1*128 + h]), acc1);
            acc1 = ffma2(bna, dup2(sn[kx1*128 + h]), acc1);
        }
        int b = blockIdx.x >> 6, c = blockIdx.x & 63;
        int m0 = kx0*24 + ky, m1 = kx1*24 + ky;
        g_xft_re[(m0*Bn + b)*Cn + c] = acc0.x;
        g_xft_im[(m0*Bn + b)*Cn + c] = acc0.y;
        g_xft_re[(m1*Bn + b)*Cn + c] = acc1.x;
        g_xft_im[(m1*Bn + b)*Cn + c] = acc1.y;
    }
}

// ---------------- K3: per-mode complex channel mix (512 thr) --------------
__global__ void __launch_bounds__(512) k3_mix(const float* __restrict__ wr_g,
                                              const float* __restrict__ wi_g) {
    __shared__ float xr_s[1024], xi_s[1024];
    __shared__ float wr_s[4096], wi_s[4096];
    int m = blockIdx.x, tid = threadIdx.x;
    for (int i = tid; i < 1024; i += 512) {
        xr_s[i] = g_xft_re[m*1024 + i];
        xi_s[i] = g_xft_im[m*1024 + i];
    }
    for (int i = tid; i < 4096; i += 512) {
        wr_s[i] = wr_g[(size_t)m*4096 + i];
        wi_s[i] = wi_g[(size_t)m*4096 + i];
    }
    __syncthreads();

    int b  = tid >> 5;
    int og = tid & 31;
    float2 re = make_float2(0.f, 0.f), im = make_float2(0.f, 0.f);
    #pragma unroll 4
    for (int c = 0; c < 64; c++) {
        float xr = xr_s[b*64 + c];
        float xi = xi_s[b*64 + c];
        float2 wr = *(const float2*)&wr_s[c*64 + 2*og];
        float2 wi = *(const float2*)&wi_s[c*64 + 2*og];
        re = ffma2(dup2(xr),  wr, re);
        re = ffma2(dup2(-xi), wi, re);
        im = ffma2(dup2(xr),  wi, im);
        im = ffma2(dup2(xi),  wr, im);
    }
    size_t base = (((size_t)b*576 + m)*64 + 2*og)*2;
    *(float4*)&g_oftI[base] = make_float4(re.x, im.x, re.y, im.y);
}

// ---------------- K5: per-pixel register kernel ----------------------------
// smem (floats):
//   SrT  [48][64]  3072   ([hr*24+ky][o], scaled)
//   SiT  [48][64]  3072   (negated)
//   wskT [c][64]   4096
//   f1wT [c][32]   2048
//   f2wT [k][64]   2048
//   cw   [24][128] 3072
//   sw   [24][128] 3072
//   b1 32, b2 64, gs 64
#define OFF_SRT   0
#define OFF_SIT   3072
#define OFF_WSKT  6144
#define OFF_F1WT  10240
#define OFF_F2WT  12288
#define OFF_CW    14336
#define OFF_SW    17408
#define OFF_B1    20480
#define OFF_B2    20512
#define OFF_GS    20576
#define SMEM_K5_FLOATS 20640

__global__ void __launch_bounds__(256, 2) k5_final(
    const float* __restrict__ x,
    const float* __restrict__ wsk_g,
    const float* __restrict__ f1w_g, const float* __restrict__ f1b_g,
    const float* __restrict__ f2w_g, const float* __restrict__ f2b_g,
    const float* __restrict__ gate_g,
    float* __restrict__ out)
{
    extern __shared__ float sm[];
    float* SrT  = sm + OFF_SRT;
    float* SiT  = sm + OFF_SIT;
    float* wskT = sm + OFF_WSKT;
    float* f1wT = sm + OFF_F1WT;
    float* f2wT = sm + OFF_F2WT;
    float* cw   = sm + OFF_CW;
    float* sw   = sm + OFF_SW;
    float* b1s  = sm + OFF_B1;
    float* b2s  = sm + OFF_B2;
    float* gs   = sm + OFF_GS;

    int tid = threadIdx.x;
    int w   = tid & 127;
    int hr  = tid >> 7;
    int hb  = blockIdx.x;          // rows 2*hb, 2*hb+1
    int b   = blockIdx.y;
    int h   = 2*hb + hr;

    // ---- cooperative loads (weights + trig only) ----
    for (int i = tid; i < 4096; i += 256) {
        int o = i >> 6, c = i & 63;
        wskT[c*64 + o] = wsk_g[i];
    }
    for (int i = tid; i < 2048; i += 256) {
        int k = i >> 6, c = i & 63;
        f1wT[c*32 + k] = f1w_g[i];
    }
    for (int i = tid; i < 2048; i += 256) {
        int o = i >> 5, k = i & 31;
        f2wT[k*64 + o] = f2w_g[i];
    }
    for (int i = tid; i < 3072; i += 256) { cw[i] = g_cos[i]; sw[i] = g_sin[i]; }
    if (tid < 32) b1s[tid] = f1b_g[tid];
    if (tid < 64) { b2s[tid] = f2b_g[tid]; gs[tid] = gate_g[tid]; }
    __syncthreads();

    // ---- head: inverse DFT over H from g_oftI (L2-resident) ----
    {
        int o  = tid & 63;
        int kg = tid >> 6;            // 0..3 -> ky = 6kg..6kg+5
        int h0 = 2*hb, h1x = 2*hb + 1;
        float2 a2[6][2];
        #pragma unroll
        for (int j = 0; j < 6; j++) {
            a2[j][0] = make_float2(0.f, 0.f);
            a2[j][1] = make_float2(0.f, 0.f);
        }
        #pragma unroll 2
        for (int kx = 0; kx < 24; kx++) {
            float c0 = cw[kx*128 + h0], s0 = sw[kx*128 + h0];
            float c1 = cw[kx*128 + h1x], s1 = sw[kx*128 + h1x];
            float2 e10 = make_float2(c0, s0), e20 = make_float2(-s0, c0);
            float2 e11 = make_float2(c1, s1), e21 = make_float2(-s1, c1);
            size_t mb = (((size_t)b*576 + kx*24 + 6*kg)*64 + o)*2;
            #pragma unroll
            for (int j = 0; j < 6; j++) {
                float2 v = *(const float2*)&g_oftI[mb + (size_t)j*128];
                a2[j][0] = ffma2(dup2(v.x), e10, a2[j][0]);
                a2[j][0] = ffma2(dup2(v.y), e20, a2[j][0]);
                a2[j][1] = ffma2(dup2(v.x), e11, a2[j][1]);
                a2[j][1] = ffma2(dup2(v.y), e21, a2[j][1]);
            }
        }
        const float sc = 1.0f/16384.0f;
        #pragma unroll
        for (int j = 0; j < 6; j++) {
            int ky = 6*kg + j;
            float s = (ky == 0) ? sc : 2.0f*sc;
            SrT[ky*64 + o]        =  s*a2[j][0].x;
            SiT[ky*64 + o]        = -s*a2[j][0].y;
            SrT[(24 + ky)*64 + o] =  s*a2[j][1].x;
            SiT[(24 + ky)*64 + o] = -s*a2[j][1].y;
        }
    }

    // ---- phase 1: skip (S-independent; overlaps head stores) ----
    float2 acc[32];
    #pragma unroll
    for (int i = 0; i < 32; i++) acc[i] = make_float2(0.f, 0.f);

    const float* xp = x + (((size_t)b*64)*128 + h)*128 + w;
    #pragma unroll 4
    for (int c = 0; c < 64; c++) {
        float2 xd = dup2(xp[(size_t)c*16384]);
        const float* wr = &wskT[c*64];
        #pragma unroll
        for (int g = 0; g < 16; g++) {
            float4 q = *(const float4*)&wr[4*g];
            acc[2*g]   = ffma2(xd, make_float2(q.x, q.y), acc[2*g]);
            acc[2*g+1] = ffma2(xd, make_float2(q.z, q.w), acc[2*g+1]);
        }
    }
    __syncthreads();   // S visible

    // ---- phase 2: spectral (inverse DFT over W) ----
    const float* SrR = SrT + hr*24*64;
    const float* SiR = SiT + hr*24*64;
    #pragma unroll 2
    for (int ky = 0; ky < 24; ky++) {
        float2 cd = dup2(cw[ky*128 + w]);
        float2 sd = dup2(sw[ky*128 + w]);
        const float* rr = &SrR[ky*64];
        const float* ii = &SiR[ky*64];
        #pragma unroll
        for (int g = 0; g < 16; g++) {
            float4 r = *(const float4*)&rr[4*g];
            float4 m = *(const float4*)&ii[4*g];
            acc[2*g]   = ffma2(make_float2(r.x, r.y), cd, acc[2*g]);
            acc[2*g]   = ffma2(make_float2(m.x, m.y), sd, acc[2*g]);
            acc[2*g+1] = ffma2(make_float2(r.z, r.w), cd, acc[2*g+1]);
            acc[2*g+1] = ffma2(make_float2(m.z, m.w), sd, acc[2*g+1]);
        }
    }

    // ---- h1 = gelu(acc) in place ----
    #pragma unroll
    for (int i = 0; i < 32; i++) {
        acc[i].x = gelu_f(acc[i].x);
        acc[i].y = gelu_f(acc[i].y);
    }

    // ---- fc1 (h1 in regs, weights broadcast) ----
    float2 accz[16];
    #pragma unroll
    for (int i = 0; i < 16; i++) accz[i] = make_float2(0.f, 0.f);
    #pragma unroll
    for (int c = 0; c < 64; c++) {
        float hv = (c & 1) ? acc[c >> 1].y : acc[c >> 1].x;
        float2 hd = dup2(hv);
        const float* fr = &f1wT[c*32];
        #pragma unroll
        for (int g = 0; g < 8; g++) {
            float4 q = *(const float4*)&fr[4*g];
            accz[2*g]   = ffma2(hd, make_float2(q.x, q.y), accz[2*g]);
            accz[2*g+1] = ffma2(hd, make_float2(q.z, q.w), accz[2*g+1]);
        }
    }
    // z = gelu(accz + b1) in place
    #pragma unroll
    for (int g = 0; g < 16; g++) {
        float2 bb = *(const float2*)&b1s[2*g];
        accz[g].x = gelu_f(accz[g].x + bb.x);
        accz[g].y = gelu_f(accz[g].y + bb.y);
    }

    // ---- fc2 + bias + gate*h1 (acc becomes output in place) ----
    #pragma unroll
    for (int g = 0; g < 32; g++) {
        float2 bb = *(const float2*)&b2s[2*g];
        float2 gg = *(const float2*)&gs[2*g];
        acc[g] = ffma2(gg, acc[g], bb);   // acc held h1
    }
    #pragma unroll
    for (int k = 0; k < 32; k++) {
        float zv = (k & 1) ? accz[k >> 1].y : accz[k >> 1].x;
        float2 zd = dup2(zv);
        const float* fr = &f2wT[k*64];
        #pragma unroll
        for (int g = 0; g < 16; g++) {
            float4 q = *(const float4*)&fr[4*g];
            acc[2*g]   = ffma2(zd, make_float2(q.x, q.y), acc[2*g]);
            acc[2*g+1] = ffma2(zd, make_float2(q.z, q.w), acc[2*g+1]);
        }
    }

    // ---- store (coalesced per o) ----
    float* op = out + (((size_t)b*64)*128 + h)*128 + w;
    #pragma unroll 8
    for (int o = 0; o < 64; o++) {
        float v = (o & 1) ? acc[o >> 1].y : acc[o >> 1].x;
        op[(size_t)o*16384] = v;
    }
}

// ---------------- launch ----------------
extern "C" void kernel_launch(void* const* d_in, const int* in_sizes, int n_in,
                              void* d_out, int out_size) {
    const float* x    = (const float*)d_in[0];
    const float* wre  = (const float*)d_in[1];
    const float* wim  = (const float*)d_in[2];
    const float* wsk  = (const float*)d_in[3];
    const float* f1w  = (const float*)d_in[4];
    const float* f1b  = (const float*)d_in[5];
    const float* f2w  = (const float*)d_in[6];
    const float* f2b  = (const float*)d_in[7];
    const float* gate = (const float*)d_in[8];
    float* out = (float*)d_out;

    cudaFuncSetAttribute(kA_dft, cudaFuncAttributeMaxDynamicSharedMemorySize,
                         KA_SMEM_FLOATS * (int)sizeof(float));
    cudaFuncSetAttribute(k5_final, cudaFuncAttributeMaxDynamicSharedMemorySize,
                         SMEM_K5_FLOATS * (int)sizeof(float));

    k0_init<<<6, 512>>>();
    kA_dft<<<1024, 384, KA_SMEM_FLOATS * sizeof(float)>>>(x);
    k3_mix<<<576, 512>>>(wre, wim);
    dim3 g5(64, 16);
    k5_final<<<g5, 256, SMEM_K5_FLOATS * sizeof(float)>>>(
        x, wsk, f1w, f1b, f2w, f2b, gate, out);
}

// round 11
// speedup vs baseline: 1.3273x; 1.3273x over previous
#include <cuda_runtime.h>
#include <math.h>
#include <stdint.h>

#define Bn 16
#define Cn 64
#define Hn 128
#define Wn 128
#define MXn 24
#define MYn 24
#define HIDn 32

// ---------------- scratch (device globals; no runtime allocation) ----------
__device__ float g_xft_re[MXn*MYn*Bn*Cn];     // [(kx*24+ky)][b][c]
__device__ float g_xft_im[MXn*MYn*Bn*Cn];
__device__ float g_oft_re[MXn*MYn*Bn*Cn];     // [m][b][o]
__device__ float g_oft_im[MXn*MYn*Bn*Cn];
__device__ float g_S_re[Bn*Hn*Cn*MYn];        // [b][h][o][ky] (scaled)
__device__ float g_S_im[Bn*Hn*Cn*MYn];
__device__ float g_cos[MYn*Wn];               // cos(2*pi*k*p/128)
__device__ float g_sin[MYn*Wn];               // sin(2*pi*k*p/128)
__device__ float g_twT[Wn*48];                // [w][j] j<24: cos, j>=24: -sin

// ---------------- packed f32x2 helpers ----------------
__device__ __forceinline__ float2 ffma2(float2 a, float2 b, float2 c) {
    float2 r;
    asm("fma.rn.f32x2 %0, %1, %2, %3;"
        : "=l"(reinterpret_cast<unsigned long long&>(r))
        : "l"(reinterpret_cast<unsigned long long&>(a)),
          "l"(reinterpret_cast<unsigned long long&>(b)),
          "l"(reinterpret_cast<unsigned long long&>(c)));
    return r;
}
__device__ __forceinline__ float2 dup2(float x) { return make_float2(x, x); }

__device__ __forceinline__ float gelu_f(float v) {
    return 0.5f*v*(1.0f + erff(v*0.7071067811865476f));
}

// ---------------- K0: twiddle init ----------------
__global__ void k0_init() {
    int i = blockIdx.x*blockDim.x + threadIdx.x;
    if (i >= MYn*Wn) return;
    int k = i / Wn, w = i % Wn;
    float s, c;
    sincospif((float)(k*w) / 64.0f, &s, &c);
    g_cos[k*Wn + w] = c;
    g_sin[k*Wn + w] = s;
    g_twT[w*48 + k]      = c;
    g_twT[w*48 + 24 + k] = -s;
}

// ---------------- kA: fused partial DFT over W then H, per (b,c) ----------
#define KA_SMEM_FLOATS 18112

__global__ void __launch_bounds__(384) kA_dft(const float* __restrict__ x) {
    extern __shared__ float sma[];
    float* Xs  = sma;            // 4224
    float* Tw  = sma + 4224;     // 1536
    float* xwr = sma + 5760;     // 3104
    float* xwi = sma + 8864;     // 3104
    float* cs  = sma + 11968;    // 3072
    float* sn  = sma + 15040;    // 3072

    int tid = threadIdx.x;
    int rg = tid & 31;
    int jg = tid >> 5;
    int row0 = blockIdx.x * 128;

    for (int i = tid; i < 3072; i += 384) { cs[i] = g_cos[i]; sn[i] = g_sin[i]; }

    float2 acc[2][4];
    #pragma unroll
    for (int i = 0; i < 2; i++)
        #pragma unroll
        for (int j = 0; j < 4; j++) acc[i][j] = make_float2(0.f, 0.f);

    for (int kt = 0; kt < 4; kt++) {
        for (int i = tid; i < 4096; i += 384) {
            int r = i >> 5, w = i & 31;
            Xs[w*132 + r] = x[(size_t)(row0 + r)*128 + kt*32 + w];
        }
        for (int i = tid; i < 32*48; i += 384)
            Tw[i] = g_twT[kt*32*48 + i];
        __syncthreads();
        #pragma unroll
        for (int kk = 0; kk < 32; kk++) {
            float4 xa = *(const float4*)&Xs[kk*132 + 4*rg];
            float2 xp0 = make_float2(xa.x, xa.y);
            float2 xp1 = make_float2(xa.z, xa.w);
            float4 tq = *(const float4*)&Tw[kk*48 + 4*jg];
            float tv[4] = { tq.x, tq.y, tq.z, tq.w };
            #pragma unroll
            for (int j = 0; j < 4; j++) {
                float2 td = dup2(tv[j]);
                acc[0][j] = ffma2(xp0, td, acc[0][j]);
                acc[1][j] = ffma2(xp1, td, acc[1][j]);
            }
        }
        __syncthreads();
    }

    {
        float* dst = (jg < 6) ? xwr : xwi;
        int colbase = (jg < 6) ? (4*jg) : (4*jg - 24);
        #pragma unroll
        for (int i = 0; i < 4; i++) {
            int pair = i >> 1, half = i & 1;
            int h = 4*rg + i;
            #pragma unroll
            for (int j = 0; j < 4; j++) {
                float v = half ? acc[pair][j].y : acc[pair][j].x;
                dst[(colbase + j)*129 + h] = v;
            }
        }
    }
    __syncthreads();

    if (tid < 288) {
        int ky  = tid % 24;
        int kxg = tid / 24;
        int kx0 = 2*kxg, kx1 = 2*kxg + 1;
        float2 acc0 = make_float2(0.f, 0.f);
        float2 acc1 = make_float2(0.f, 0.f);
        #pragma unroll 4
        for (int h = 0; h < 128; h++) {
            float a = xwr[ky*129 + h];
            float b = xwi[ky*129 + h];
            float2 ab  = make_float2(a, b);
            float2 bna = make_float2(b, -a);
            acc0 = ffma2(ab,  dup2(cs[kx0*128 + h]), acc0);
            acc0 = ffma2(bna, dup2(sn[kx0*128 + h]), acc0);
            acc1 = ffma2(ab,  dup2(cs[kx1*128 + h]), acc1);
            acc1 = ffma2(bna, dup2(sn[kx1*128 + h]), acc1);
        }
        int b = blockIdx.x >> 6, c = blockIdx.x & 63;
        int m0 = kx0*24 + ky, m1 = kx1*24 + ky;
        g_xft_re[(m0*Bn + b)*Cn + c] = acc0.x;
        g_xft_im[(m0*Bn + b)*Cn + c] = acc0.y;
        g_xft_re[(m1*Bn + b)*Cn + c] = acc1.x;
        g_xft_im[(m1*Bn + b)*Cn + c] = acc1.y;
    }
}

// ---------------- K3: per-mode complex channel mix (512 thr) --------------
__global__ void __launch_bounds__(512) k3_mix(const float* __restrict__ wr_g,
                                              const float* __restrict__ wi_g) {
    __shared__ float xr_s[1024], xi_s[1024];
    __shared__ float wr_s[4096], wi_s[4096];
    int m = blockIdx.x, tid = threadIdx.x;
    for (int i = tid; i < 1024; i += 512) {
        xr_s[i] = g_xft_re[m*1024 + i];
        xi_s[i] = g_xft_im[m*1024 + i];
    }
    for (int i = tid; i < 4096; i += 512) {
        wr_s[i] = wr_g[(size_t)m*4096 + i];
        wi_s[i] = wi_g[(size_t)m*4096 + i];
    }
    __syncthreads();

    int b  = tid >> 5;
    int og = tid & 31;
    float2 re = make_float2(0.f, 0.f), im = make_float2(0.f, 0.f);
    #pragma unroll 4
    for (int c = 0; c < 64; c++) {
        float xr = xr_s[b*64 + c];
        float xi = xi_s[b*64 + c];
        float2 wr = *(const float2*)&wr_s[c*64 + 2*og];
        float2 wi = *(const float2*)&wi_s[c*64 + 2*og];
        re = ffma2(dup2(xr),  wr, re);
        re = ffma2(dup2(-xi), wi, re);
        im = ffma2(dup2(xr),  wi, im);
        im = ffma2(dup2(xi),  wr, im);
    }
    int base = (m*Bn + b)*Cn + 2*og;
    *(float2*)&g_oft_re[base] = re;
    *(float2*)&g_oft_im[base] = im;
}

// ---------------- K4: inverse DFT over H (scale folded) ----------------
__global__ void __launch_bounds__(128) k4_idftH() {
    __shared__ float osm[576*2];
    __shared__ float cs[24*128], sn[24*128];
    int bx = blockIdx.x;
    int b = bx >> 6, o = bx & 63;
    int tid = threadIdx.x;
    for (int i = tid; i < 576; i += 128) {
        osm[2*i]   = g_oft_re[i*1024 + b*64 + o];
        osm[2*i+1] = g_oft_im[i*1024 + b*64 + o];
    }
    for (int i = tid; i < 3072; i += 128) { cs[i] = g_cos[i]; sn[i] = g_sin[i]; }
    __syncthreads();

    int h = tid;
    float2 acc[24];
    #pragma unroll
    for (int ky = 0; ky < 24; ky++) acc[ky] = make_float2(0.f, 0.f);
    #pragma unroll 2
    for (int kx = 0; kx < 24; kx++) {
        float cr = cs[kx*128 + h];
        float si = sn[kx*128 + h];
        float2 v1 = make_float2(cr, si);
        float2 v2 = make_float2(-si, cr);
        #pragma unroll
        for (int ky = 0; ky < 24; ky++) {
            float2 ov = *(const float2*)&osm[(kx*24 + ky)*2];
            acc[ky] = ffma2(dup2(ov.x), v1, acc[ky]);
            acc[ky] = ffma2(dup2(ov.y), v2, acc[ky]);
        }
    }
    size_t base = (((size_t)b*128 + h)*64 + o)*24;
    const float sc = 1.0f/16384.0f;
    #pragma unroll
    for (int ky = 0; ky < 24; ky++) {
        float s = (ky == 0) ? sc : 2.0f*sc;
        g_S_re[base + ky] = acc[ky].x*s;
        g_S_im[base + ky] = acc[ky].y*s;
    }
}

// ---------------- K5: 1-row GEMM kernel, 256 thr, 2 CTAs/SM ---------------
// smem floats:
//   h1s  [64][128] 8192
//   zs   [32][128] 4096
//   SrT  [24][64]  1536   ([ky][o], scaled)
//   SiT  [24][64]  1536   (negated)
//   wskT [c][64]   4096
//   f1wT [c][32]   2048
//   f2wT [k][64]   2048
//   tc   [24][64]  1536   (cos, w<64; w>=64 via (-1)^ky symmetry)
//   ts   [24][64]  1536
//   b1 32, b2 64, gs 64
#define OFF5_H1   0
#define OFF5_ZS   8192
#define OFF5_SR   12288
#define OFF5_SI   13824
#define OFF5_WSK  15360
#define OFF5_F1   19456
#define OFF5_F2   21504
#define OFF5_TC   23552
#define OFF5_TS   25088
#define OFF5_B1   26624
#define OFF5_B2   26656
#define OFF5_GS   26720
#define SMEM_K5_FLOATS 26784

__global__ void __launch_bounds__(256, 2) k5_final(
    const float* __restrict__ x,
    const float* __restrict__ wsk_g,
    const float* __restrict__ f1w_g, const float* __restrict__ f1b_g,
    const float* __restrict__ f2w_g, const float* __restrict__ f2b_g,
    const float* __restrict__ gate_g,
    float* __restrict__ out)
{
    extern __shared__ float sm[];
    float* h1s  = sm + OFF5_H1;
    float* zs   = sm + OFF5_ZS;
    float* SrT  = sm + OFF5_SR;
    float* SiT  = sm + OFF5_SI;
    float* wskT = sm + OFF5_WSK;
    float* f1wT = sm + OFF5_F1;
    float* f2wT = sm + OFF5_F2;
    float* tc   = sm + OFF5_TC;
    float* ts   = sm + OFF5_TS;
    float* b1s  = sm + OFF5_B1;
    float* b2s  = sm + OFF5_B2;
    float* gs   = sm + OFF5_GS;

    int tid  = threadIdx.x;
    int lane = tid & 31;
    int wid  = tid >> 5;          // 0..7
    int o0   = wid * 8;
    int w0   = lane * 4;
    int h    = blockIdx.x;
    int b    = blockIdx.y;

    // ---- cooperative loads ----
    for (int i = tid; i < 4096; i += 256) {
        int o = i >> 6, c = i & 63;
        wskT[c*64 + o] = wsk_g[i];
    }
    for (int i = tid; i < 2048; i += 256) {
        int k = i >> 6, c = i & 63;
        f1wT[c*32 + k] = f1w_g[i];
    }
    for (int i = tid; i < 2048; i += 256) {
        int o = i >> 5, k = i & 31;
        f2wT[k*64 + o] = f2w_g[i];
    }
    // trig, w < 64 only
    for (int i = tid; i < 1536; i += 256) {
        int ky = i >> 6, w = i & 63;
        tc[i] = g_cos[ky*128 + w];
        ts[i] = g_sin[ky*128 + w];
    }
    // S (scaled), transposed to [ky][o]; SiT negated
    {
        size_t sb = ((size_t)b*128 + h) * (64*24);
        for (int i = tid; i < 1536; i += 256) {
            int o = i / 24, ky = i - o*24;
            SrT[ky*64 + o] =  g_S_re[sb + i];
            SiT[ky*64 + o] = -g_S_im[sb + i];
        }
    }
    if (tid < 32) b1s[tid] = f1b_g[tid];
    if (tid < 64) { b2s[tid] = f2b_g[tid]; gs[tid] = gate_g[tid]; }

    // ---- phase 1: skip, x from global (no smem dependency -> before sync) --
    float2 acc[8][2];
    #pragma unroll
    for (int oo = 0; oo < 8; oo++) {
        acc[oo][0] = make_float2(0.f, 0.f);
        acc[oo][1] = make_float2(0.f, 0.f);
    }
    __syncthreads();   // tables visible (needed for wskT)

    const float* xp = x + (((size_t)b*64)*128 + h)*128 + w0;
    #pragma unroll 4
    for (int c = 0; c < 64; c++) {
        float4 xa = *(const float4*)(xp + (size_t)c*16384);
        float2 xv0 = make_float2(xa.x, xa.y);
        float2 xv1 = make_float2(xa.z, xa.w);
        float4 wa = *(const float4*)&wskT[c*64 + o0];
        float4 wb = *(const float4*)&wskT[c*64 + o0 + 4];
        float wv[8] = { wa.x, wa.y, wa.z, wa.w, wb.x, wb.y, wb.z, wb.w };
        #pragma unroll
        for (int oo = 0; oo < 8; oo++) {
            float2 wd = dup2(wv[oo]);
            acc[oo][0] = ffma2(wd, xv0, acc[oo][0]);
            acc[oo][1] = ffma2(wd, xv1, acc[oo][1]);
        }
    }

    // ---- phase 2: spectral (inverse DFT over W, trig symmetry) ----
    int wq = w0 & 63;
    float signbase = (w0 >= 64) ? -1.0f : 1.0f;
    #pragma unroll 2
    for (int ky = 0; ky < 24; ky++) {
        float s = (ky & 1) ? signbase : 1.0f;
        float4 ca = *(const float4*)&tc[ky*64 + wq];
        float4 sa = *(const float4*)&ts[ky*64 + wq];
        float2 cv0 = make_float2(s*ca.x, s*ca.y);
        float2 cv1 = make_float2(s*ca.z, s*ca.w);
        float2 sv0 = make_float2(s*sa.x, s*sa.y);
        float2 sv1 = make_float2(s*sa.z, s*sa.w);
        float4 ra = *(const float4*)&SrT[ky*64 + o0];
        float4 rb = *(const float4*)&SrT[ky*64 + o0 + 4];
        float4 ia = *(const float4*)&SiT[ky*64 + o0];
        float4 ib = *(const float4*)&SiT[ky*64 + o0 + 4];
        float rv[8] = { ra.x, ra.y, ra.z, ra.w, rb.x, rb.y, rb.z, rb.w };
        float iv[8] = { ia.x, ia.y, ia.z, ia.w, ib.x, ib.y, ib.z, ib.w };
        #pragma unroll
        for (int oo = 0; oo < 8; oo++) {
            float2 rd = dup2(rv[oo]);
            float2 id = dup2(iv[oo]);
            acc[oo][0] = ffma2(rd, cv0, acc[oo][0]);
            acc[oo][0] = ffma2(id, sv0, acc[oo][0]);
            acc[oo][1] = ffma2(rd, cv1, acc[oo][1]);
            acc[oo][1] = ffma2(id, sv1, acc[oo][1]);
        }
    }

    // h1 = gelu(spec + skip); keep in regs + smem
    float h1r[8][4];
    #pragma unroll
    for (int oo = 0; oo < 8; oo++) {
        h1r[oo][0] = gelu_f(acc[oo][0].x);
        h1r[oo][1] = gelu_f(acc[oo][0].y);
        h1r[oo][2] = gelu_f(acc[oo][1].x);
        h1r[oo][3] = gelu_f(acc[oo][1].y);
        *(float4*)&h1s[(o0+oo)*128 + w0] =
            make_float4(h1r[oo][0], h1r[oo][1], h1r[oo][2], h1r[oo][3]);
    }
    __syncthreads();

    // ---- phase 3: fc1 + gelu -> zs ----
    int k0 = wid * 4;
    float2 acc2[4][2];
    #pragma unroll
    for (int kk = 0; kk < 4; kk++) {
        acc2[kk][0] = make_float2(0.f, 0.f);
        acc2[kk][1] = make_float2(0.f, 0.f);
    }
    #pragma unroll 2
    for (int c = 0; c < 64; c++) {
        float4 ha = *(const float4*)&h1s[c*128 + w0];
        float2 hv0 = make_float2(ha.x, ha.y);
        float2 hv1 = make_float2(ha.z, ha.w);
        float4 fv = *(const float4*)&f1wT[c*32 + k0];
        float fw[4] = { fv.x, fv.y, fv.z, fv.w };
        #pragma unroll
        for (int kk = 0; kk < 4; kk++) {
            float2 fd = dup2(fw[kk]);
            acc2[kk][0] = ffma2(fd, hv0, acc2[kk][0]);
            acc2[kk][1] = ffma2(fd, hv1, acc2[kk][1]);
        }
    }
    #pragma unroll
    for (int kk = 0; kk < 4; kk++) {
        float bb = b1s[k0+kk];
        *(float4*)&zs[(k0+kk)*128 + w0] = make_float4(
            gelu_f(acc2[kk][0].x + bb), gelu_f(acc2[kk][0].y + bb),
            gelu_f(acc2[kk][1].x + bb), gelu_f(acc2[kk][1].y + bb));
    }
    __syncthreads();

    // ---- phase 4: fc2 + bias + gate*h1 ----
    float2 acc3[8][2];
    #pragma unroll
    for (int oo = 0; oo < 8; oo++) {
        float bb = b2s[o0+oo];
        acc3[oo][0] = make_float2(bb, bb);
        acc3[oo][1] = make_float2(bb, bb);
    }
    #pragma unroll 2
    for (int k = 0; k < 32; k++) {
        float4 za = *(const float4*)&zs[k*128 + w0];
        float2 zv0 = make_float2(za.x, za.y);
        float2 zv1 = make_float2(za.z, za.w);
        float4 fa = *(const float4*)&f2wT[k*64 + o0];
        float4 fb = *(const float4*)&f2wT[k*64 + o0 + 4];
        float fw[8] = { fa.x, fa.y, fa.z, fa.w, fb.x, fb.y, fb.z, fb.w };
        #pragma unroll
        for (int oo = 0; oo < 8; oo++) {
            float2 fd = dup2(fw[oo]);
            acc3[oo][0] = ffma2(fd, zv0, acc3[oo][0]);
            acc3[oo][1] = ffma2(fd, zv1, acc3[oo][1]);
        }
    }
    #pragma unroll
    for (int oo = 0; oo < 8; oo++) {
        float g = gs[o0+oo];
        float4 r = make_float4(acc3[oo][0].x + g*h1r[oo][0],
                               acc3[oo][0].y + g*h1r[oo][1],
                               acc3[oo][1].x + g*h1r[oo][2],
                               acc3[oo][1].y + g*h1r[oo][3]);
        *(float4*)&out[(((size_t)b*64 + (o0+oo))*128 + h)*128 + w0] = r;
    }
}

// ---------------- launch ----------------
extern "C" void kernel_launch(void* const* d_in, const int* in_sizes, int n_in,
                              void* d_out, int out_size) {
    const float* x    = (const float*)d_in[0];
    const float* wre  = (const float*)d_in[1];
    const float* wim  = (const float*)d_in[2];
    const float* wsk  = (const float*)d_in[3];
    const float* f1w  = (const float*)d_in[4];
    const float* f1b  = (const float*)d_in[5];
    const float* f2w  = (const float*)d_in[6];
    const float* f2b  = (const float*)d_in[7];
    const float* gate = (const float*)d_in[8];
    float* out = (float*)d_out;

    cudaFuncSetAttribute(kA_dft, cudaFuncAttributeMaxDynamicSharedMemorySize,
                         KA_SMEM_FLOATS * (int)sizeof(float));
    cudaFuncSetAttribute(k5_final, cudaFuncAttributeMaxDynamicSharedMemorySize,
                         SMEM_K5_FLOATS * (int)sizeof(float));

    k0_init<<<6, 512>>>();
    kA_dft<<<1024, 384, KA_SMEM_FLOATS * sizeof(float)>>>(x);
    k3_mix<<<576, 512>>>(wre, wim);
    k4_idftH<<<1024, 128>>>();
    dim3 g5(128, 16);
    k5_final<<<g5, 256, SMEM_K5_FLOATS * sizeof(float)>>>(
        x, wsk, f1w, f1b, f2w, f2b, gate, out);
}

// round 13
// speedup vs baseline: 1.4745x; 1.1109x over previous
#include <cuda_runtime.h>
#include <math.h>
#include <stdint.h>

#define Bn 16
#define Cn 64
#define Hn 128
#define Wn 128
#define MXn 24
#define MYn 24
#define HIDn 32

// ---------------- scratch (device globals; no runtime allocation) ----------
__device__ float g_xft_re[MXn*MYn*Bn*Cn];     // [(kx*24+ky)][b][c]
__device__ float g_xft_im[MXn*MYn*Bn*Cn];
__device__ float g_oft_re[MXn*MYn*Bn*Cn];     // [m][b][o]
__device__ float g_oft_im[MXn*MYn*Bn*Cn];
__device__ float g_S_re[Bn*Hn*MYn*Cn];        // [b][h][ky][o]  scaled
__device__ float g_S_im[Bn*Hn*MYn*Cn];        // [b][h][ky][o]  scaled, NEGATED
__device__ float g_cos[MYn*Wn];               // cos(2*pi*k*p/128)
__device__ float g_sin[MYn*Wn];               // sin(2*pi*k*p/128)
__device__ float g_twT[Wn*48];                // [w][j] j<24: cos, j>=24: -sin

// ---------------- packed f32x2 helpers ----------------
__device__ __forceinline__ float2 ffma2(float2 a, float2 b, float2 c) {
    float2 r;
    asm("fma.rn.f32x2 %0, %1, %2, %3;"
        : "=l"(reinterpret_cast<unsigned long long&>(r))
        : "l"(reinterpret_cast<unsigned long long&>(a)),
          "l"(reinterpret_cast<unsigned long long&>(b)),
          "l"(reinterpret_cast<unsigned long long&>(c)));
    return r;
}
__device__ __forceinline__ float2 dup2(float x) { return make_float2(x, x); }

__device__ __forceinline__ float gelu_f(float v) {
    return 0.5f*v*(1.0f + erff(v*0.7071067811865476f));
}

// ---------------- K0: twiddle init ----------------
__global__ void k0_init() {
    int i = blockIdx.x*blockDim.x + threadIdx.x;
    if (i >= MYn*Wn) return;
    int k = i / Wn, w = i % Wn;
    float s, c;
    sincospif((float)(k*w) / 64.0f, &s, &c);
    g_cos[k*Wn + w] = c;
    g_sin[k*Wn + w] = s;
    g_twT[w*48 + k]      = c;
    g_twT[w*48 + 24 + k] = -s;
}

// ---------------- kA: fused partial DFT over W then H, per (b,c) ----------
// Xs stride 132 (multiple of 4 -> LDS.128 alignment preserved)
#define KA_SMEM_FLOATS 18112

__global__ void __launch_bounds__(384) kA_dft(const float* __restrict__ x) {
    extern __shared__ float sma[];
    float* Xs  = sma;            // 4224  (32x132)
    float* Tw  = sma + 4224;     // 1536
    float* xwr = sma + 5760;     // 3104
    float* xwi = sma + 8864;     // 3104
    float* cs  = sma + 11968;    // 3072
    float* sn  = sma + 15040;    // 3072

    int tid = threadIdx.x;
    int rg = tid & 31;
    int jg = tid >> 5;
    int row0 = blockIdx.x * 128;

    for (int i = tid; i < 3072; i += 384) { cs[i] = g_cos[i]; sn[i] = g_sin[i]; }

    float2 acc[2][4];
    #pragma unroll
    for (int i = 0; i < 2; i++)
        #pragma unroll
        for (int j = 0; j < 4; j++) acc[i][j] = make_float2(0.f, 0.f);

    for (int kt = 0; kt < 4; kt++) {
        for (int i = tid; i < 4096; i += 384) {
            int r = i >> 5, w = i & 31;
            Xs[w*132 + r] = x[(size_t)(row0 + r)*128 + kt*32 + w];
        }
        for (int i = tid; i < 32*48; i += 384)
            Tw[i] = g_twT[kt*32*48 + i];
        __syncthreads();
        #pragma unroll
        for (int kk = 0; kk < 32; kk++) {
            float4 xa = *(const float4*)&Xs[kk*132 + 4*rg];
            float2 xp0 = make_float2(xa.x, xa.y);
            float2 xp1 = make_float2(xa.z, xa.w);
            float4 tq = *(const float4*)&Tw[kk*48 + 4*jg];
            float tv[4] = { tq.x, tq.y, tq.z, tq.w };
            #pragma unroll
            for (int j = 0; j < 4; j++) {
                float2 td = dup2(tv[j]);
                acc[0][j] = ffma2(xp0, td, acc[0][j]);
                acc[1][j] = ffma2(xp1, td, acc[1][j]);
            }
        }
        __syncthreads();
    }

    {
        float* dst = (jg < 6) ? xwr : xwi;
        int colbase = (jg < 6) ? (4*jg) : (4*jg - 24);
        #pragma unroll
        for (int i = 0; i < 4; i++) {
            int pair = i >> 1, half = i & 1;
            int h = 4*rg + i;
            #pragma unroll
            for (int j = 0; j < 4; j++) {
                float v = half ? acc[pair][j].y : acc[pair][j].x;
                dst[(colbase + j)*129 + h] = v;
            }
        }
    }
    __syncthreads();

    if (tid < 288) {
        int ky  = tid % 24;
        int kxg = tid / 24;
        int kx0 = 2*kxg, kx1 = 2*kxg + 1;
        float2 acc0 = make_float2(0.f, 0.f);
        float2 acc1 = make_float2(0.f, 0.f);
        #pragma unroll 4
        for (int h = 0; h < 128; h++) {
            float a = xwr[ky*129 + h];
            float b = xwi[ky*129 + h];
            float2 ab  = make_float2(a, b);
            float2 bna = make_float2(b, -a);
            acc0 = ffma2(ab,  dup2(cs[kx0*128 + h]), acc0);
            acc0 = ffma2(bna, dup2(sn[kx0*128 + h]), acc0);
            acc1 = ffma2(ab,  dup2(cs[kx1*128 + h]), acc1);
            acc1 = ffma2(bna, dup2(sn[kx1*128 + h]), acc1);
        }
        int b = blockIdx.x >> 6, c = blockIdx.x & 63;
        int m0 = kx0*24 + ky, m1 = kx1*24 + ky;
        g_xft_re[(m0*Bn + b)*Cn + c] = acc0.x;
        g_xft_im[(m0*Bn + b)*Cn + c] = acc0.y;
        g_xft_re[(m1*Bn + b)*Cn + c] = acc1.x;
        g_xft_im[(m1*Bn + b)*Cn + c] = acc1.y;
    }
}

// ---------------- K3: per-mode complex channel mix (512 thr) --------------
__global__ void __launch_bounds__(512) k3_mix(const float* __restrict__ wr_g,
                                              const float* __restrict__ wi_g) {
    __shared__ float xr_s[1024], xi_s[1024];
    __shared__ float wr_s[4096], wi_s[4096];
    int m = blockIdx.x, tid = threadIdx.x;
    for (int i = tid; i < 1024; i += 512) {
        xr_s[i] = g_xft_re[m*1024 + i];
        xi_s[i] = g_xft_im[m*1024 + i];
    }
    for (int i = tid; i < 4096; i += 512) {
        wr_s[i] = wr_g[(size_t)m*4096 + i];
        wi_s[i] = wi_g[(size_t)m*4096 + i];
    }
    __syncthreads();

    int b  = tid >> 5;
    int og = tid & 31;
    float2 re = make_float2(0.f, 0.f), im = make_float2(0.f, 0.f);
    #pragma unroll 4
    for (int c = 0; c < 64; c++) {
        float xr = xr_s[b*64 + c];
        float xi = xi_s[b*64 + c];
        float2 wr = *(const float2*)&wr_s[c*64 + 2*og];
        float2 wi = *(const float2*)&wi_s[c*64 + 2*og];
        re = ffma2(dup2(xr),  wr, re);
        re = ffma2(dup2(-xi), wi, re);
        im = ffma2(dup2(xr),  wi, im);
        im = ffma2(dup2(xi),  wr, im);
    }
    int base = (m*Bn + b)*Cn + 2*og;
    *(float2*)&g_oft_re[base] = re;
    *(float2*)&g_oft_im[base] = im;
}

// ---------------- K4: inverse DFT over H -> S[b][h][ky][o] ----------------
// block = (b, 4 h-rows); threads = 64 o x 4 ky-groups (6 ky each)
#define K4_SMEM_FLOATS 18624

__global__ void __launch_bounds__(256) k4_idftH() {
    extern __shared__ float sm4[];
    float* osr = sm4;            // [144 modes][64 o]
    float* osi = sm4 + 9216;
    float* tcs = sm4 + 18432;    // [24 kx][4 h]
    float* tsn = sm4 + 18528;

    int bx = blockIdx.x;
    int b  = bx >> 5;
    int h0 = (bx & 31) * 4;
    int tid = threadIdx.x;
    int o   = tid & 63;
    int ky0 = (tid >> 6) * 6;

    if (tid < 96) {
        int kx = tid >> 2, hh = tid & 3;
        tcs[kx*4 + hh] = g_cos[kx*128 + h0 + hh];
        tsn[kx*4 + hh] = g_sin[kx*128 + h0 + hh];
    }

    float2 acc[4][6];
    #pragma unroll
    for (int hh = 0; hh < 4; hh++)
        #pragma unroll
        for (int j = 0; j < 6; j++) acc[hh][j] = make_float2(0.f, 0.f);

    for (int ch = 0; ch < 4; ch++) {
        __syncthreads();
        for (int i = tid; i < 9216; i += 256) {
            int m = ch*144 + (i >> 6);
            int oo = i & 63;
            osr[i] = g_oft_re[(m*Bn + b)*Cn + oo];
            osi[i] = g_oft_im[(m*Bn + b)*Cn + oo];
        }
        __syncthreads();
        #pragma unroll
        for (int kxl = 0; kxl < 6; kxl++) {
            int kx = ch*6 + kxl;
            float cr4[4], si4[4];
            #pragma unroll
            for (int hh = 0; hh < 4; hh++) {
                cr4[hh] = tcs[kx*4 + hh];
                si4[hh] = tsn[kx*4 + hh];
            }
            #pragma unroll
            for (int j = 0; j < 6; j++) {
                float re = osr[(kxl*24 + ky0 + j)*64 + o];
                float im = osi[(kxl*24 + ky0 + j)*64 + o];
                float2 red = dup2(re), imd = dup2(im);
                #pragma unroll
                for (int hh = 0; hh < 4; hh++) {
                    float2 v1 = make_float2(cr4[hh], si4[hh]);
                    float2 v2 = make_float2(-si4[hh], cr4[hh]);
                    acc[hh][j] = ffma2(red, v1, acc[hh][j]);
                    acc[hh][j] = ffma2(imd, v2, acc[hh][j]);
                }
            }
        }
    }
    const float sc = 1.0f/16384.0f;
    #pragma unroll
    for (int hh = 0; hh < 4; hh++) {
        #pragma unroll
        for (int j = 0; j < 6; j++) {
            int ky = ky0 + j;
            float s = (ky == 0) ? sc : 2.0f*sc;
            size_t base = (((size_t)b*128 + h0 + hh)*24 + ky)*64 + o;
            g_S_re[base] =  s*acc[hh][j].x;
            g_S_im[base] = -s*acc[hh][j].y;   // pre-negated for k5
        }
    }
}

// ---------------- K5: 1-row GEMM, x staged in h1s, 2 CTAs/SM --------------
#define OFF5_H1   0
#define OFF5_ZS   8192
#define OFF5_SR   12288
#define OFF5_SI   13824
#define OFF5_WSK  15360
#define OFF5_F1   19456
#define OFF5_F2   21504
#define OFF5_TC   23552
#define OFF5_TS   25088
#define OFF5_B1   26624
#define OFF5_B2   26656
#define OFF5_GS   26720
#define SMEM_K5_FLOATS 26784

__global__ void __launch_bounds__(256, 2) k5_final(
    const float* __restrict__ x,
    const float* __restrict__ wsk_g,
    const float* __restrict__ f1w_g, const float* __restrict__ f1b_g,
    const float* __restrict__ f2w_g, const float* __restrict__ f2b_g,
    const float* __restrict__ gate_g,
    float* __restrict__ out)
{
    extern __shared__ float sm[];
    float* h1s  = sm + OFF5_H1;
    float* zs   = sm + OFF5_ZS;
    float* SrT  = sm + OFF5_SR;
    float* SiT  = sm + OFF5_SI;
    float* wskT = sm + OFF5_WSK;
    float* f1wT = sm + OFF5_F1;
    float* f2wT = sm + OFF5_F2;
    float* tc   = sm + OFF5_TC;
    float* ts   = sm + OFF5_TS;
    float* b1s  = sm + OFF5_B1;
    float* b2s  = sm + OFF5_B2;
    float* gs   = sm + OFF5_GS;

    int tid  = threadIdx.x;
    int lane = tid & 31;
    int wid  = tid >> 5;          // 0..7
    int o0   = wid * 8;
    int w0   = lane * 4;
    int h    = blockIdx.x;
    int b    = blockIdx.y;

    // ---- stage x into h1s (coalesced) ----
    const float* xb = x + ((size_t)b*64*128 + h)*128;
    for (int i = tid; i < 2048; i += 256) {
        int c = i >> 5, w4 = (i & 31) * 4;
        *(float4*)&h1s[c*128 + w4] = *(const float4*)&xb[(size_t)c*16384 + w4];
    }
    // ---- tables ----
    for (int i = tid; i < 4096; i += 256) {
        int o = i >> 6, c = i & 63;
        wskT[c*64 + o] = wsk_g[i];
    }
    for (int i = tid; i < 2048; i += 256) {
        int k = i >> 6, c = i & 63;
        f1wT[c*32 + k] = f1w_g[i];
    }
    for (int i = tid; i < 2048; i += 256) {
        int o = i >> 5, k = i & 31;
        f2wT[k*64 + o] = f2w_g[i];
    }
    for (int i = tid; i < 1536; i += 256) {
        int ky = i >> 6, w = i & 63;
        tc[i] = g_cos[ky*128 + w];
        ts[i] = g_sin[ky*128 + w];
    }
    {
        size_t sb = ((size_t)b*128 + h) * 1536;
        for (int i = tid; i < 384; i += 256) {
            *(float4*)&SrT[i*4] = *(const float4*)&g_S_re[sb + (size_t)i*4];
            *(float4*)&SiT[i*4] = *(const float4*)&g_S_im[sb + (size_t)i*4];
        }
    }
    if (tid < 32) b1s[tid] = f1b_g[tid];
    if (tid < 64) { b2s[tid] = f2b_g[tid]; gs[tid] = gate_g[tid]; }
    __syncthreads();   // S1

    // ---- phase 1: skip (x from h1s) ----
    float2 acc[8][2];
    #pragma unroll
    for (int oo = 0; oo < 8; oo++) {
        acc[oo][0] = make_float2(0.f, 0.f);
        acc[oo][1] = make_float2(0.f, 0.f);
    }
    #pragma unroll 4
    for (int c = 0; c < 64; c++) {
        float4 xa = *(const float4*)&h1s[c*128 + w0];
        float2 xv0 = make_float2(xa.x, xa.y);
        float2 xv1 = make_float2(xa.z, xa.w);
        float4 wa = *(const float4*)&wskT[c*64 + o0];
        float4 wb = *(const float4*)&wskT[c*64 + o0 + 4];
        float wv[8] = { wa.x, wa.y, wa.z, wa.w, wb.x, wb.y, wb.z, wb.w };
        #pragma unroll
        for (int oo = 0; oo < 8; oo++) {
            float2 wd = dup2(wv[oo]);
            acc[oo][0] = ffma2(wd, xv0, acc[oo][0]);
            acc[oo][1] = ffma2(wd, xv1, acc[oo][1]);
        }
    }

    // ---- phase 2: spectral (inverse DFT over W, trig symmetry) ----
    int wq = w0 & 63;
    float signbase = (w0 >= 64) ? -1.0f : 1.0f;
    #pragma unroll 2
    for (int ky = 0; ky < 24; ky++) {
        float s = (ky & 1) ? signbase : 1.0f;
        float4 ca = *(const float4*)&tc[ky*64 + wq];
        float4 sa = *(const float4*)&ts[ky*64 + wq];
        float2 cv0 = make_float2(s*ca.x, s*ca.y);
        float2 cv1 = make_float2(s*ca.z, s*ca.w);
        float2 sv0 = make_float2(s*sa.x, s*sa.y);
        float2 sv1 = make_float2(s*sa.z, s*sa.w);
        float4 ra = *(const float4*)&SrT[ky*64 + o0];
        float4 rb = *(const float4*)&SrT[ky*64 + o0 + 4];
        float4 ia = *(const float4*)&SiT[ky*64 + o0];
        float4 ib = *(const float4*)&SiT[ky*64 + o0 + 4];
        float rv[8] = { ra.x, ra.y, ra.z, ra.w, rb.x, rb.y, rb.z, rb.w };
        float iv[8] = { ia.x, ia.y, ia.z, ia.w, ib.x, ib.y, ib.z, ib.w };
        #pragma unroll
        for (int oo = 0; oo < 8; oo++) {
            float2 rd = dup2(rv[oo]);
            float2 id = dup2(iv[oo]);
            acc[oo][0] = ffma2(rd, cv0, acc[oo][0]);
            acc[oo][0] = ffma2(id, sv0, acc[oo][0]);
            acc[oo][1] = ffma2(rd, cv1, acc[oo][1]);
            acc[oo][1] = ffma2(id, sv1, acc[oo][1]);
        }
    }

    // h1 = gelu(spec + skip)
    float h1v[8][4];
    #pragma unroll
    for (int oo = 0; oo < 8; oo++) {
        h1v[oo][0] = gelu_f(acc[oo][0].x);
        h1v[oo][1] = gelu_f(acc[oo][0].y);
        h1v[oo][2] = gelu_f(acc[oo][1].x);
        h1v[oo][3] = gelu_f(acc[oo][1].y);
    }
    __syncthreads();   // S2: all x reads done -> safe to overwrite h1s
    #pragma unroll
    for (int oo = 0; oo < 8; oo++)
        *(float4*)&h1s[(o0+oo)*128 + w0] =
            make_float4(h1v[oo][0], h1v[oo][1], h1v[oo][2], h1v[oo][3]);
    __syncthreads();   // S3

    // ---- phase 3: fc1 + gelu -> zs ----
    int k0 = wid * 4;
    float2 acc2[4][2];
    #pragma unroll
    for (int kk = 0; kk < 4; kk++) {
        acc2[kk][0] = make_float2(0.f, 0.f);
        acc2[kk][1] = make_float2(0.f, 0.f);
    }
    #pragma unroll 4
    for (int c = 0; c < 64; c++) {
        float4 ha = *(const float4*)&h1s[c*128 + w0];
        float2 hv0 = make_float2(ha.x, ha.y);
        float2 hv1 = make_float2(ha.z, ha.w);
        float4 fv = *(const float4*)&f1wT[c*32 + k0];
        float fw[4] = { fv.x, fv.y, fv.z, fv.w };
        #pragma unroll
        for (int kk = 0; kk < 4; kk++) {
            float2 fd = dup2(fw[kk]);
            acc2[kk][0] = ffma2(fd, hv0, acc2[kk][0]);
            acc2[kk][1] = ffma2(fd, hv1, acc2[kk][1]);
        }
    }
    #pragma unroll
    for (int kk = 0; kk < 4; kk++) {
        float bb = b1s[k0+kk];
        *(float4*)&zs[(k0+kk)*128 + w0] = make_float4(
            gelu_f(acc2[kk][0].x + bb), gelu_f(acc2[kk][0].y + bb),
            gelu_f(acc2[kk][1].x + bb), gelu_f(acc2[kk][1].y + bb));
    }
    __syncthreads();   // S4

    // ---- phase 4: fc2 + bias + gate*h1 ----
    float2 acc3[8][2];
    #pragma unroll
    for (int oo = 0; oo < 8; oo++) {
        float bb = b2s[o0+oo];
        acc3[oo][0] = make_float2(bb, bb);
        acc3[oo][1] = make_float2(bb, bb);
    }
    #pragma unroll 4
    for (int k = 0; k < 32; k++) {
        float4 za = *(const float4*)&zs[k*128 + w0];
        float2 zv0 = make_float2(za.x, za.y);
        float2 zv1 = make_float2(za.z, za.w);
        float4 fa = *(const float4*)&f2wT[k*64 + o0];
        float4 fb = *(const float4*)&f2wT[k*64 + o0 + 4];
        float fw[8] = { fa.x, fa.y, fa.z, fa.w, fb.x, fb.y, fb.z, fb.w };
        #pragma unroll
        for (int oo = 0; oo < 8; oo++) {
            float2 fd = dup2(fw[oo]);
            acc3[oo][0] = ffma2(fd, zv0, acc3[oo][0]);
            acc3[oo][1] = ffma2(fd, zv1, acc3[oo][1]);
        }
    }
    #pragma unroll
    for (int oo = 0; oo < 8; oo++) {
        float g = gs[o0+oo];
        float4 hh = *(const float4*)&h1s[(o0+oo)*128 + w0];
        float4 r = make_float4(acc3[oo][0].x + g*hh.x,
                               acc3[oo][0].y + g*hh.y,
                               acc3[oo][1].x + g*hh.z,
                               acc3[oo][1].y + g*hh.w);
        *(float4*)&out[(((size_t)b*64 + (o0+oo))*128 + h)*128 + w0] = r;
    }
}

// ---------------- launch ----------------
extern "C" void kernel_launch(void* const* d_in, const int* in_sizes, int n_in,
                              void* d_out, int out_size) {
    const float* x    = (const float*)d_in[0];
    const float* wre  = (const float*)d_in[1];
    const float* wim  = (const float*)d_in[2];
    const float* wsk  = (const float*)d_in[3];
    const float* f1w  = (const float*)d_in[4];
    const float* f1b  = (const float*)d_in[5];
    const float* f2w  = (const float*)d_in[6];
    const float* f2b  = (const float*)d_in[7];
    const float* gate = (const float*)d_in[8];
    float* out = (float*)d_out;

    cudaFuncSetAttribute(kA_dft, cudaFuncAttributeMaxDynamicSharedMemorySize,
                         KA_SMEM_FLOATS * (int)sizeof(float));
    cudaFuncSetAttribute(k4_idftH, cudaFuncAttributeMaxDynamicSharedMemorySize,
                         K4_SMEM_FLOATS * (int)sizeof(float));
    cudaFuncSetAttribute(k5_final, cudaFuncAttributeMaxDynamicSharedMemorySize,
                         SMEM_K5_FLOATS * (int)sizeof(float));

    k0_init<<<6, 512>>>();
    kA_dft<<<1024, 384, KA_SMEM_FLOATS * sizeof(float)>>>(x);
    k3_mix<<<576, 512>>>(wre, wim);
    k4_idftH<<<512, 256, K4_SMEM_FLOATS * sizeof(float)>>>();
    dim3 g5(128, 16);
    k5_final<<<g5, 256, SMEM_K5_FLOATS * sizeof(float)>>>(
        x, wsk, f1w, f1b, f2w, f2b, gate, out);
}

// round 14
// speedup vs baseline: 1.5545x; 1.0543x over previous
#include <cuda_runtime.h>
#include <math.h>
#include <stdint.h>

#define Bn 16
#define Cn 64
#define Hn 128
#define Wn 128
#define MXn 24
#define MYn 24
#define HIDn 32

// ---------------- scratch (device globals; no runtime allocation) ----------
__device__ float g_xft_re[MXn*MYn*Bn*Cn];     // [(kx*24+ky)][b][c]
__device__ float g_xft_im[MXn*MYn*Bn*Cn];
__device__ float g_oftI[MXn*MYn*Bn*Cn*2];     // [m][b][o][re,im]
__device__ float g_S_re[Bn*Hn*MYn*Cn];        // [b][h][ky][o]  scaled
__device__ float g_S_im[Bn*Hn*MYn*Cn];        // [b][h][ky][o]  scaled, NEGATED
__device__ float g_cos[MYn*Wn];               // cos(2*pi*k*p/128)
__device__ float g_sin[MYn*Wn];               // sin(2*pi*k*p/128)
__device__ float g_twT[Wn*48];                // [w][j] j<24: cos, j>=24: -sin

// ---------------- packed f32x2 helpers ----------------
__device__ __forceinline__ float2 ffma2(float2 a, float2 b, float2 c) {
    float2 r;
    asm("fma.rn.f32x2 %0, %1, %2, %3;"
        : "=l"(reinterpret_cast<unsigned long long&>(r))
        : "l"(reinterpret_cast<unsigned long long&>(a)),
          "l"(reinterpret_cast<unsigned long long&>(b)),
          "l"(reinterpret_cast<unsigned long long&>(c)));
    return r;
}
__device__ __forceinline__ float2 dup2(float x) { return make_float2(x, x); }

__device__ __forceinline__ float gelu_f(float v) {
    return 0.5f*v*(1.0f + erff(v*0.7071067811865476f));
}

// ---------------- K0: twiddle init ----------------
__global__ void k0_init() {
    int i = blockIdx.x*blockDim.x + threadIdx.x;
    if (i >= MYn*Wn) return;
    int k = i / Wn, w = i % Wn;
    float s, c;
    sincospif((float)(k*w) / 64.0f, &s, &c);
    g_cos[k*Wn + w] = c;
    g_sin[k*Wn + w] = s;
    g_twT[w*48 + k]      = c;
    g_twT[w*48 + 24 + k] = -s;
}

// ---------------- kA: fused partial DFT over W then H, per (b,c) ----------
#define KA_SMEM_FLOATS 18112

__global__ void __launch_bounds__(384) kA_dft(const float* __restrict__ x) {
    extern __shared__ float sma[];
    float* Xs  = sma;            // 4224  (32x132)
    float* Tw  = sma + 4224;     // 1536
    float* xwr = sma + 5760;     // 3104
    float* xwi = sma + 8864;     // 3104
    float* cs  = sma + 11968;    // 3072
    float* sn  = sma + 15040;    // 3072

    int tid = threadIdx.x;
    int rg = tid & 31;
    int jg = tid >> 5;
    int row0 = blockIdx.x * 128;

    for (int i = tid; i < 3072; i += 384) { cs[i] = g_cos[i]; sn[i] = g_sin[i]; }

    float2 acc[2][4];
    #pragma unroll
    for (int i = 0; i < 2; i++)
        #pragma unroll
        for (int j = 0; j < 4; j++) acc[i][j] = make_float2(0.f, 0.f);

    for (int kt = 0; kt < 4; kt++) {
        for (int i = tid; i < 4096; i += 384) {
            int r = i >> 5, w = i & 31;
            Xs[w*132 + r] = x[(size_t)(row0 + r)*128 + kt*32 + w];
        }
        for (int i = tid; i < 32*48; i += 384)
            Tw[i] = g_twT[kt*32*48 + i];
        __syncthreads();
        #pragma unroll
        for (int kk = 0; kk < 32; kk++) {
            float4 xa = *(const float4*)&Xs[kk*132 + 4*rg];
            float2 xp0 = make_float2(xa.x, xa.y);
            float2 xp1 = make_float2(xa.z, xa.w);
            float4 tq = *(const float4*)&Tw[kk*48 + 4*jg];
            float tv[4] = { tq.x, tq.y, tq.z, tq.w };
            #pragma unroll
            for (int j = 0; j < 4; j++) {
                float2 td = dup2(tv[j]);
                acc[0][j] = ffma2(xp0, td, acc[0][j]);
                acc[1][j] = ffma2(xp1, td, acc[1][j]);
            }
        }
        __syncthreads();
    }

    {
        float* dst = (jg < 6) ? xwr : xwi;
        int colbase = (jg < 6) ? (4*jg) : (4*jg - 24);
        #pragma unroll
        for (int i = 0; i < 4; i++) {
            int pair = i >> 1, half = i & 1;
            int h = 4*rg + i;
            #pragma unroll
            for (int j = 0; j < 4; j++) {
                float v = half ? acc[pair][j].y : acc[pair][j].x;
                dst[(colbase + j)*129 + h] = v;
            }
        }
    }
    __syncthreads();

    if (tid < 288) {
        int ky  = tid % 24;
        int kxg = tid / 24;
        int kx0 = 2*kxg, kx1 = 2*kxg + 1;
        float2 acc0 = make_float2(0.f, 0.f);
        float2 acc1 = make_float2(0.f, 0.f);
        #pragma unroll 4
        for (int h = 0; h < 128; h++) {
            float a = xwr[ky*129 + h];
            float b = xwi[ky*129 + h];
            float2 ab  = make_float2(a, b);
            float2 bna = make_float2(b, -a);
            acc0 = ffma2(ab,  dup2(cs[kx0*128 + h]), acc0);
            acc0 = ffma2(bna, dup2(sn[kx0*128 + h]), acc0);
            acc1 = ffma2(ab,  dup2(cs[kx1*128 + h]), acc1);
            acc1 = ffma2(bna, dup2(sn[kx1*128 + h]), acc1);
        }
        int b = blockIdx.x >> 6, c = blockIdx.x & 63;
        int m0 = kx0*24 + ky, m1 = kx1*24 + ky;
        g_xft_re[(m0*Bn + b)*Cn + c] = acc0.x;
        g_xft_im[(m0*Bn + b)*Cn + c] = acc0.y;
        g_xft_re[(m1*Bn + b)*Cn + c] = acc1.x;
        g_xft_im[(m1*Bn + b)*Cn + c] = acc1.y;
    }
}

// ---------------- K3: per-mode complex channel mix (512 thr) --------------
__global__ void __launch_bounds__(512) k3_mix(const float* __restrict__ wr_g,
                                              const float* __restrict__ wi_g) {
    __shared__ float xr_s[1024], xi_s[1024];
    __shared__ float wr_s[4096], wi_s[4096];
    int m = blockIdx.x, tid = threadIdx.x;
    for (int i = tid; i < 1024; i += 512) {
        xr_s[i] = g_xft_re[m*1024 + i];
        xi_s[i] = g_xft_im[m*1024 + i];
    }
    for (int i = tid; i < 4096; i += 512) {
        wr_s[i] = wr_g[(size_t)m*4096 + i];
        wi_s[i] = wi_g[(size_t)m*4096 + i];
    }
    __syncthreads();

    int b  = tid >> 5;
    int og = tid & 31;
    float2 re = make_float2(0.f, 0.f), im = make_float2(0.f, 0.f);
    #pragma unroll 4
    for (int c = 0; c < 64; c++) {
        float xr = xr_s[b*64 + c];
        float xi = xi_s[b*64 + c];
        float2 wr = *(const float2*)&wr_s[c*64 + 2*og];
        float2 wi = *(const float2*)&wi_s[c*64 + 2*og];
        re = ffma2(dup2(xr),  wr, re);
        re = ffma2(dup2(-xi), wi, re);
        im = ffma2(dup2(xr),  wi, im);
        im = ffma2(dup2(xi),  wr, im);
    }
    // interleaved write: [m][b][o][re,im]
    size_t base = ((size_t)(m*Bn + b)*Cn + 2*og)*2;
    *(float4*)&g_oftI[base] = make_float4(re.x, im.x, re.y, im.y);
}

// ---------------- K4: inverse DFT over H, direct-L2 reads ----------------
// block = (b, 4 h-rows), grid 512; 384 thr = 64 o x 6 ky-groups (4 ky each)
__global__ void __launch_bounds__(384) k4_idftH() {
    __shared__ float tcs[24*4], tsn[24*4];

    int bx = blockIdx.x;
    int b  = bx >> 5;
    int h0 = (bx & 31) * 4;
    int tid = threadIdx.x;
    int o   = tid & 63;
    int ky0 = (tid >> 6) * 4;     // 0,4,...,20

    if (tid < 96) {
        int kx = tid >> 2, hh = tid & 3;
        tcs[kx*4 + hh] = g_cos[kx*128 + h0 + hh];
        tsn[kx*4 + hh] = g_sin[kx*128 + h0 + hh];
    }
    __syncthreads();

    float2 acc[4][4];   // [hh][j]
    #pragma unroll
    for (int hh = 0; hh < 4; hh++)
        #pragma unroll
        for (int j = 0; j < 4; j++) acc[hh][j] = make_float2(0.f, 0.f);

    #pragma unroll 2
    for (int kx = 0; kx < 24; kx++) {
        // batch 4 independent L2 loads (oftI is L2-resident: 4.7MB)
        float2 v[4];
        size_t mb = ((size_t)((kx*24 + ky0)*Bn + b)*Cn + o)*2;
        #pragma unroll
        for (int j = 0; j < 4; j++)
            v[j] = *(const float2*)&g_oftI[mb + (size_t)j*(Bn*Cn*2)];
        float cr4[4], si4[4];
        #pragma unroll
        for (int hh = 0; hh < 4; hh++) {
            cr4[hh] = tcs[kx*4 + hh];
            si4[hh] = tsn[kx*4 + hh];
        }
        #pragma unroll
        for (int j = 0; j < 4; j++) {
            float2 red = dup2(v[j].x), imd = dup2(v[j].y);
            #pragma unroll
            for (int hh = 0; hh < 4; hh++) {
                float2 e1 = make_float2(cr4[hh], si4[hh]);
                float2 e2 = make_float2(-si4[hh], cr4[hh]);
                acc[hh][j] = ffma2(red, e1, acc[hh][j]);
                acc[hh][j] = ffma2(imd, e2, acc[hh][j]);
            }
        }
    }

    const float sc = 1.0f/16384.0f;
    #pragma unroll
    for (int hh = 0; hh < 4; hh++) {
        #pragma unroll
        for (int j = 0; j < 4; j++) {
            int ky = ky0 + j;
            float s = (ky == 0) ? sc : 2.0f*sc;
            size_t base = (((size_t)b*128 + h0 + hh)*24 + ky)*64 + o;
            g_S_re[base] =  s*acc[hh][j].x;
            g_S_im[base] = -s*acc[hh][j].y;   // pre-negated for k5
        }
    }
}

// ---------------- K5: 1-row GEMM, x staged in h1s, 2 CTAs/SM --------------
#define OFF5_H1   0
#define OFF5_ZS   8192
#define OFF5_SR   12288
#define OFF5_SI   13824
#define OFF5_WSK  15360
#define OFF5_F1   19456
#define OFF5_F2   21504
#define OFF5_TC   23552
#define OFF5_TS   25088
#define OFF5_B1   26624
#define OFF5_B2   26656
#define OFF5_GS   26720
#define SMEM_K5_FLOATS 26784

__global__ void __launch_bounds__(256, 2) k5_final(
    const float* __restrict__ x,
    const float* __restrict__ wsk_g,
    const float* __restrict__ f1w_g, const float* __restrict__ f1b_g,
    const float* __restrict__ f2w_g, const float* __restrict__ f2b_g,
    const float* __restrict__ gate_g,
    float* __restrict__ out)
{
    extern __shared__ float sm[];
    float* h1s  = sm + OFF5_H1;
    float* zs   = sm + OFF5_ZS;
    float* SrT  = sm + OFF5_SR;
    float* SiT  = sm + OFF5_SI;
    float* wskT = sm + OFF5_WSK;
    float* f1wT = sm + OFF5_F1;
    float* f2wT = sm + OFF5_F2;
    float* tc   = sm + OFF5_TC;
    float* ts   = sm + OFF5_TS;
    float* b1s  = sm + OFF5_B1;
    float* b2s  = sm + OFF5_B2;
    float* gs   = sm + OFF5_GS;

    int tid  = threadIdx.x;
    int lane = tid & 31;
    int wid  = tid >> 5;          // 0..7
    int o0   = wid * 8;
    int w0   = lane * 4;
    int h    = blockIdx.x;
    int b    = blockIdx.y;

    // ---- stage x into h1s (coalesced) ----
    const float* xb = x + ((size_t)b*64*128 + h)*128;
    for (int i = tid; i < 2048; i += 256) {
        int c = i >> 5, w4 = (i & 31) * 4;
        *(float4*)&h1s[c*128 + w4] = *(const float4*)&xb[(size_t)c*16384 + w4];
    }
    // ---- tables ----
    for (int i = tid; i < 4096; i += 256) {
        int o = i >> 6, c = i & 63;
        wskT[c*64 + o] = wsk_g[i];
    }
    for (int i = tid; i < 2048; i += 256) {
        int k = i >> 6, c = i & 63;
        f1wT[c*32 + k] = f1w_g[i];
    }
    for (int i = tid; i < 2048; i += 256) {
        int o = i >> 5, k = i & 31;
        f2wT[k*64 + o] = f2w_g[i];
    }
    for (int i = tid; i < 1536; i += 256) {
        int ky = i >> 6, w = i & 63;
        tc[i] = g_cos[ky*128 + w];
        ts[i] = g_sin[ky*128 + w];
    }
    {
        size_t sb = ((size_t)b*128 + h) * 1536;
        for (int i = tid; i < 384; i += 256) {
            *(float4*)&SrT[i*4] = *(const float4*)&g_S_re[sb + (size_t)i*4];
            *(float4*)&SiT[i*4] = *(const float4*)&g_S_im[sb + (size_t)i*4];
        }
    }
    if (tid < 32) b1s[tid] = f1b_g[tid];
    if (tid < 64) { b2s[tid] = f2b_g[tid]; gs[tid] = gate_g[tid]; }
    __syncthreads();   // S1

    // ---- phase 1: skip (x from h1s) ----
    float2 acc[8][2];
    #pragma unroll
    for (int oo = 0; oo < 8; oo++) {
        acc[oo][0] = make_float2(0.f, 0.f);
        acc[oo][1] = make_float2(0.f, 0.f);
    }
    #pragma unroll 4
    for (int c = 0; c < 64; c++) {
        float4 xa = *(const float4*)&h1s[c*128 + w0];
        float2 xv0 = make_float2(xa.x, xa.y);
        float2 xv1 = make_float2(xa.z, xa.w);
        float4 wa = *(const float4*)&wskT[c*64 + o0];
        float4 wb = *(const float4*)&wskT[c*64 + o0 + 4];
        float wv[8] = { wa.x, wa.y, wa.z, wa.w, wb.x, wb.y, wb.z, wb.w };
        #pragma unroll
        for (int oo = 0; oo < 8; oo++) {
            float2 wd = dup2(wv[oo]);
            acc[oo][0] = ffma2(wd, xv0, acc[oo][0]);
            acc[oo][1] = ffma2(wd, xv1, acc[oo][1]);
        }
    }

    // ---- phase 2: spectral (inverse DFT over W, trig symmetry) ----
    int wq = w0 & 63;
    float signbase = (w0 >= 64) ? -1.0f : 1.0f;
    #pragma unroll 2
    for (int ky = 0; ky < 24; ky++) {
        float s = (ky & 1) ? signbase : 1.0f;
        float4 ca = *(const float4*)&tc[ky*64 + wq];
        float4 sa = *(const float4*)&ts[ky*64 + wq];
        float2 cv0 = make_float2(s*ca.x, s*ca.y);
        float2 cv1 = make_float2(s*ca.z, s*ca.w);
        float2 sv0 = make_float2(s*sa.x, s*sa.y);
        float2 sv1 = make_float2(s*sa.z, s*sa.w);
        float4 ra = *(const float4*)&SrT[ky*64 + o0];
        float4 rb = *(const float4*)&SrT[ky*64 + o0 + 4];
        float4 ia = *(const float4*)&SiT[ky*64 + o0];
        float4 ib = *(const float4*)&SiT[ky*64 + o0 + 4];
        float rv[8] = { ra.x, ra.y, ra.z, ra.w, rb.x, rb.y, rb.z, rb.w };
        float iv[8] = { ia.x, ia.y, ia.z, ia.w, ib.x, ib.y, ib.z, ib.w };
        #pragma unroll
        for (int oo = 0; oo < 8; oo++) {
            float2 rd = dup2(rv[oo]);
            float2 id = dup2(iv[oo]);
            acc[oo][0] = ffma2(rd, cv0, acc[oo][0]);
            acc[oo][0] = ffma2(id, sv0, acc[oo][0]);
            acc[oo][1] = ffma2(rd, cv1, acc[oo][1]);
            acc[oo][1] = ffma2(id, sv1, acc[oo][1]);
        }
    }

    // h1 = gelu(spec + skip)
    float h1v[8][4];
    #pragma unroll
    for (int oo = 0; oo < 8; oo++) {
        h1v[oo][0] = gelu_f(acc[oo][0].x);
        h1v[oo][1] = gelu_f(acc[oo][0].y);
        h1v[oo][2] = gelu_f(acc[oo][1].x);
        h1v[oo][3] = gelu_f(acc[oo][1].y);
    }
    __syncthreads();   // S2: all x reads done -> safe to overwrite h1s
    #pragma unroll
    for (int oo = 0; oo < 8; oo++)
        *(float4*)&h1s[(o0+oo)*128 + w0] =
            make_float4(h1v[oo][0], h1v[oo][1], h1v[oo][2], h1v[oo][3]);
    __syncthreads();   // S3

    // ---- phase 3: fc1 + gelu -> zs ----
    int k0 = wid * 4;
    float2 acc2[4][2];
    #pragma unroll
    for (int kk = 0; kk < 4; kk++) {
        acc2[kk][0] = make_float2(0.f, 0.f);
        acc2[kk][1] = make_float2(0.f, 0.f);
    }
    #pragma unroll 4
    for (int c = 0; c < 64; c++) {
        float4 ha = *(const float4*)&h1s[c*128 + w0];
        float2 hv0 = make_float2(ha.x, ha.y);
        float2 hv1 = make_float2(ha.z, ha.w);
        float4 fv = *(const float4*)&f1wT[c*32 + k0];
        float fw[4] = { fv.x, fv.y, fv.z, fv.w };
        #pragma unroll
        for (int kk = 0; kk < 4; kk++) {
            float2 fd = dup2(fw[kk]);
            acc2[kk][0] = ffma2(fd, hv0, acc2[kk][0]);
            acc2[kk][1] = ffma2(fd, hv1, acc2[kk][1]);
        }
    }
    #pragma unroll
    for (int kk = 0; kk < 4; kk++) {
        float bb = b1s[k0+kk];
        *(float4*)&zs[(k0+kk)*128 + w0] = make_float4(
            gelu_f(acc2[kk][0].x + bb), gelu_f(acc2[kk][0].y + bb),
            gelu_f(acc2[kk][1].x + bb), gelu_f(acc2[kk][1].y + bb));
    }
    __syncthreads();   // S4

    // ---- phase 4: fc2 + bias + gate*h1 ----
    float2 acc3[8][2];
    #pragma unroll
    for (int oo = 0; oo < 8; oo++) {
        float bb = b2s[o0+oo];
        acc3[oo][0] = make_float2(bb, bb);
        acc3[oo][1] = make_float2(bb, bb);
    }
    #pragma unroll 4
    for (int k = 0; k < 32; k++) {
        float4 za = *(const float4*)&zs[k*128 + w0];
        float2 zv0 = make_float2(za.x, za.y);
        float2 zv1 = make_float2(za.z, za.w);
        float4 fa = *(const float4*)&f2wT[k*64 + o0];
        float4 fb = *(const float4*)&f2wT[k*64 + o0 + 4];
        float fw[8] = { fa.x, fa.y, fa.z, fa.w, fb.x, fb.y, fb.z, fb.w };
        #pragma unroll
        for (int oo = 0; oo < 8; oo++) {
            float2 fd = dup2(fw[oo]);
            acc3[oo][0] = ffma2(fd, zv0, acc3[oo][0]);
            acc3[oo][1] = ffma2(fd, zv1, acc3[oo][1]);
        }
    }
    #pragma unroll
    for (int oo = 0; oo < 8; oo++) {
        float g = gs[o0+oo];
        float4 hh = *(const float4*)&h1s[(o0+oo)*128 + w0];
        float4 r = make_float4(acc3[oo][0].x + g*hh.x,
                               acc3[oo][0].y + g*hh.y,
                               acc3[oo][1].x + g*hh.z,
                               acc3[oo][1].y + g*hh.w);
        *(float4*)&out[(((size_t)b*64 + (o0+oo))*128 + h)*128 + w0] = r;
    }
}

// ---------------- launch ----------------
extern "C" void kernel_launch(void* const* d_in, const int* in_sizes, int n_in,
                              void* d_out, int out_size) {
    const float* x    = (const float*)d_in[0];
    const float* wre  = (const float*)d_in[1];
    const float* wim  = (const float*)d_in[2];
    const float* wsk  = (const float*)d_in[3];
    const float* f1w  = (const float*)d_in[4];
    const float* f1b  = (const float*)d_in[5];
    const float* f2w  = (const float*)d_in[6];
    const float* f2b  = (const float*)d_in[7];
    const float* gate = (const float*)d_in[8];
    float* out = (float*)d_out;

    cudaFuncSetAttribute(kA_dft, cudaFuncAttributeMaxDynamicSharedMemorySize,
                         KA_SMEM_FLOATS * (int)sizeof(float));
    cudaFuncSetAttribute(k5_final, cudaFuncAttributeMaxDynamicSharedMemorySize,
                         SMEM_K5_FLOATS * (int)sizeof(float));

    k0_init<<<6, 512>>>();
    kA_dft<<<1024, 384, KA_SMEM_FLOATS * sizeof(float)>>>(x);
    k3_mix<<<576, 512>>>(wre, wim);
    k4_idftH<<<512, 384>>>();
    dim3 g5(128, 16);
    k5_final<<<g5, 256, SMEM_K5_FLOATS * sizeof(float)>>>(
        x, wsk, f1w, f1b, f2w, f2b, gate, out);
}

// round 15
// speedup vs baseline: 1.9557x; 1.2581x over previous
#include <cuda_runtime.h>
#include <math.h>
#include <stdint.h>

#define Bn 16
#define Cn 64
#define Hn 128
#define Wn 128
#define MXn 24
#define MYn 24
#define HIDn 32

// ---------------- scratch (device globals; no runtime allocation) ----------
__device__ float g_xft_re[MXn*MYn*Bn*Cn];     // [(kx*24+ky)][b][c]
__device__ float g_xft_im[MXn*MYn*Bn*Cn];
__device__ float g_oftI[MXn*MYn*Bn*Cn*2];     // [m][b][o][re,im]
__device__ float g_S_re[Bn*Hn*MYn*Cn];        // [b][h][ky][o]  scaled
__device__ float g_S_im[Bn*Hn*MYn*Cn];        // [b][h][ky][o]  scaled, NEGATED
__device__ float g_cos[MYn*Wn];               // cos(2*pi*k*p/128)
__device__ float g_sin[MYn*Wn];               // sin(2*pi*k*p/128)
__device__ float g_twT[Wn*48];                // [w][j] j<24: cos, j>=24: -sin
__device__ float g_wskT[Cn*Cn];               // [c][o]
__device__ float g_f1T[Cn*HIDn];              // [c][k]
__device__ float g_f2T[HIDn*Cn];              // [k][o]

// ---------------- packed f32x2 helpers ----------------
__device__ __forceinline__ float2 ffma2(float2 a, float2 b, float2 c) {
    float2 r;
    asm("fma.rn.f32x2 %0, %1, %2, %3;"
        : "=l"(reinterpret_cast<unsigned long long&>(r))
        : "l"(reinterpret_cast<unsigned long long&>(a)),
          "l"(reinterpret_cast<unsigned long long&>(b)),
          "l"(reinterpret_cast<unsigned long long&>(c)));
    return r;
}
__device__ __forceinline__ float2 dup2(float x) { return make_float2(x, x); }

__device__ __forceinline__ float gelu_f(float v) {
    return 0.5f*v*(1.0f + erff(v*0.7071067811865476f));
}

// ---------------- K0: twiddle init + weight transposes ----------------
__global__ void k0_init(const float* __restrict__ wsk,
                        const float* __restrict__ f1w,
                        const float* __restrict__ f2w) {
    int tid = blockIdx.x*blockDim.x + threadIdx.x;
    int nt  = gridDim.x*blockDim.x;
    for (int i = tid; i < MYn*Wn; i += nt) {
        int k = i / Wn, w = i % Wn;
        float s, c;
        sincospif((float)(k*w) / 64.0f, &s, &c);
        g_cos[k*Wn + w] = c;
        g_sin[k*Wn + w] = s;
        g_twT[w*48 + k]      = c;
        g_twT[w*48 + 24 + k] = -s;
    }
    for (int i = tid; i < 4096; i += nt) {
        int o = i >> 6, c = i & 63;
        g_wskT[c*64 + o] = wsk[i];
    }
    for (int i = tid; i < 2048; i += nt) {
        int k = i >> 6, c = i & 63;
        g_f1T[c*32 + k] = f1w[i];
    }
    for (int i = tid; i < 2048; i += nt) {
        int o = i >> 5, k = i & 31;
        g_f2T[k*64 + o] = f2w[i];
    }
}

// ---------------- kA: fused partial DFT over W then H, per (b,c) ----------
#define KA_SMEM_FLOATS 18112

__global__ void __launch_bounds__(384, 3) kA_dft(const float* __restrict__ x) {
    extern __shared__ float sma[];
    float* Xs  = sma;            // 4224  (32x132)
    float* Tw  = sma + 4224;     // 1536
    float* xwr = sma + 5760;     // 3104
    float* xwi = sma + 8864;     // 3104
    float* cs  = sma + 11968;    // 3072
    float* sn  = sma + 15040;    // 3072

    int tid = threadIdx.x;
    int rg = tid & 31;
    int jg = tid >> 5;
    int row0 = blockIdx.x * 128;

    for (int i = tid; i < 3072; i += 384) { cs[i] = g_cos[i]; sn[i] = g_sin[i]; }

    float2 acc[2][4];
    #pragma unroll
    for (int i = 0; i < 2; i++)
        #pragma unroll
        for (int j = 0; j < 4; j++) acc[i][j] = make_float2(0.f, 0.f);

    for (int kt = 0; kt < 4; kt++) {
        for (int i = tid; i < 4096; i += 384) {
            int r = i >> 5, w = i & 31;
            Xs[w*132 + r] = x[(size_t)(row0 + r)*128 + kt*32 + w];
        }
        for (int i = tid; i < 32*48; i += 384)
            Tw[i] = g_twT[kt*32*48 + i];
        __syncthreads();
        #pragma unroll
        for (int kk = 0; kk < 32; kk++) {
            float4 xa = *(const float4*)&Xs[kk*132 + 4*rg];
            float2 xp0 = make_float2(xa.x, xa.y);
            float2 xp1 = make_float2(xa.z, xa.w);
            float4 tq = *(const float4*)&Tw[kk*48 + 4*jg];
            float tv[4] = { tq.x, tq.y, tq.z, tq.w };
            #pragma unroll
            for (int j = 0; j < 4; j++) {
                float2 td = dup2(tv[j]);
                acc[0][j] = ffma2(xp0, td, acc[0][j]);
                acc[1][j] = ffma2(xp1, td, acc[1][j]);
            }
        }
        __syncthreads();
    }

    {
        float* dst = (jg < 6) ? xwr : xwi;
        int colbase = (jg < 6) ? (4*jg) : (4*jg - 24);
        #pragma unroll
        for (int i = 0; i < 4; i++) {
            int pair = i >> 1, half = i & 1;
            int h = 4*rg + i;
            #pragma unroll
            for (int j = 0; j < 4; j++) {
                float v = half ? acc[pair][j].y : acc[pair][j].x;
                dst[(colbase + j)*129 + h] = v;
            }
        }
    }
    __syncthreads();

    if (tid < 288) {
        int ky  = tid % 24;
        int kxg = tid / 24;
        int kx0 = 2*kxg, kx1 = 2*kxg + 1;
        float2 acc0 = make_float2(0.f, 0.f);
        float2 acc1 = make_float2(0.f, 0.f);
        #pragma unroll 4
        for (int h = 0; h < 128; h++) {
            float a = xwr[ky*129 + h];
            float b = xwi[ky*129 + h];
            float2 ab  = make_float2(a, b);
            float2 bna = make_float2(b, -a);
            acc0 = ffma2(ab,  dup2(cs[kx0*128 + h]), acc0);
            acc0 = ffma2(bna, dup2(sn[kx0*128 + h]), acc0);
            acc1 = ffma2(ab,  dup2(cs[kx1*128 + h]), acc1);
            acc1 = ffma2(bna, dup2(sn[kx1*128 + h]), acc1);
        }
        int b = blockIdx.x >> 6, c = blockIdx.x & 63;
        int m0 = kx0*24 + ky, m1 = kx1*24 + ky;
        g_xft_re[(m0*Bn + b)*Cn + c] = acc0.x;
        g_xft_im[(m0*Bn + b)*Cn + c] = acc0.y;
        g_xft_re[(m1*Bn + b)*Cn + c] = acc1.x;
        g_xft_im[(m1*Bn + b)*Cn + c] = acc1.y;
    }
}

// ---------------- K3: per-mode complex channel mix (512 thr) --------------
__global__ void __launch_bounds__(512) k3_mix(const float* __restrict__ wr_g,
                                              const float* __restrict__ wi_g) {
    __shared__ float xr_s[1024], xi_s[1024];
    __shared__ float wr_s[4096], wi_s[4096];
    int m = blockIdx.x, tid = threadIdx.x;
    // float4-vectorized loads
    if (tid < 256) {
        ((float4*)xr_s)[tid] = ((const float4*)g_xft_re)[m*256 + tid];
        ((float4*)xi_s)[tid] = ((const float4*)g_xft_im)[m*256 + tid];
    }
    for (int i = tid; i < 1024; i += 512) {
        ((float4*)wr_s)[i] = ((const float4*)wr_g)[(size_t)m*1024 + i];
        ((float4*)wi_s)[i] = ((const float4*)wi_g)[(size_t)m*1024 + i];
    }
    __syncthreads();

    int b  = tid >> 5;
    int og = tid & 31;
    float2 re = make_float2(0.f, 0.f), im = make_float2(0.f, 0.f);
    #pragma unroll 4
    for (int c = 0; c < 64; c++) {
        float xr = xr_s[b*64 + c];
        float xi = xi_s[b*64 + c];
        float2 wr = *(const float2*)&wr_s[c*64 + 2*og];
        float2 wi = *(const float2*)&wi_s[c*64 + 2*og];
        re = ffma2(dup2(xr),  wr, re);
        re = ffma2(dup2(-xi), wi, re);
        im = ffma2(dup2(xr),  wi, im);
        im = ffma2(dup2(xi),  wr, im);
    }
    size_t base = ((size_t)(m*Bn + b)*Cn + 2*og)*2;
    *(float4*)&g_oftI[base] = make_float4(re.x, im.x, re.y, im.y);
}

// ---------------- K4: inverse DFT over H, direct-L2 reads ----------------
__global__ void __launch_bounds__(384) k4_idftH() {
    __shared__ float tcs[24*4], tsn[24*4];

    int bx = blockIdx.x;
    int b  = bx >> 5;
    int h0 = (bx & 31) * 4;
    int tid = threadIdx.x;
    int o   = tid & 63;
    int ky0 = (tid >> 6) * 4;

    if (tid < 96) {
        int kx = tid >> 2, hh = tid & 3;
        tcs[kx*4 + hh] = g_cos[kx*128 + h0 + hh];
        tsn[kx*4 + hh] = g_sin[kx*128 + h0 + hh];
    }
    __syncthreads();

    float2 acc[4][4];
    #pragma unroll
    for (int hh = 0; hh < 4; hh++)
        #pragma unroll
        for (int j = 0; j < 4; j++) acc[hh][j] = make_float2(0.f, 0.f);

    #pragma unroll 2
    for (int kx = 0; kx < 24; kx++) {
        float2 v[4];
        size_t mb = ((size_t)((kx*24 + ky0)*Bn + b)*Cn + o)*2;
        #pragma unroll
        for (int j = 0; j < 4; j++)
            v[j] = *(const float2*)&g_oftI[mb + (size_t)j*(Bn*Cn*2)];
        float cr4[4], si4[4];
        #pragma unroll
        for (int hh = 0; hh < 4; hh++) {
            cr4[hh] = tcs[kx*4 + hh];
            si4[hh] = tsn[kx*4 + hh];
        }
        #pragma unroll
        for (int j = 0; j < 4; j++) {
            float2 red = dup2(v[j].x), imd = dup2(v[j].y);
            #pragma unroll
            for (int hh = 0; hh < 4; hh++) {
                float2 e1 = make_float2(cr4[hh], si4[hh]);
                float2 e2 = make_float2(-si4[hh], cr4[hh]);
                acc[hh][j] = ffma2(red, e1, acc[hh][j]);
                acc[hh][j] = ffma2(imd, e2, acc[hh][j]);
            }
        }
    }

    const float sc = 1.0f/16384.0f;
    #pragma unroll
    for (int hh = 0; hh < 4; hh++) {
        #pragma unroll
        for (int j = 0; j < 4; j++) {
            int ky = ky0 + j;
            float s = (ky == 0) ? sc : 2.0f*sc;
            size_t base = (((size_t)b*128 + h0 + hh)*24 + ky)*64 + o;
            g_S_re[base] =  s*acc[hh][j].x;
            g_S_im[base] = -s*acc[hh][j].y;
        }
    }
}

// ---------------- K5: 1-row GEMM, weights via uniform LDG, 3 CTAs/SM ------
#define OFF5_H1   0        // 8192   x stage -> h1
#define OFF5_ZS   8192     // 4096
#define OFF5_SR   12288    // 1536
#define OFF5_SI   13824    // 1536
#define OFF5_TC   15360    // 1536
#define OFF5_TS   16896    // 1536
#define OFF5_B1   18432    // 32
#define OFF5_B2   18464    // 64
#define OFF5_GS   18528    // 64
#define SMEM_K5_FLOATS 18592

__global__ void __launch_bounds__(256, 3) k5_final(
    const float* __restrict__ x,
    const float* __restrict__ f1b_g, const float* __restrict__ f2b_g,
    const float* __restrict__ gate_g,
    float* __restrict__ out)
{
    extern __shared__ float sm[];
    float* h1s  = sm + OFF5_H1;
    float* zs   = sm + OFF5_ZS;
    float* SrT  = sm + OFF5_SR;
    float* SiT  = sm + OFF5_SI;
    float* tc   = sm + OFF5_TC;
    float* ts   = sm + OFF5_TS;
    float* b1s  = sm + OFF5_B1;
    float* b2s  = sm + OFF5_B2;
    float* gs   = sm + OFF5_GS;

    int tid  = threadIdx.x;
    int lane = tid & 31;
    int wid  = tid >> 5;          // 0..7
    int o0   = wid * 8;
    int w0   = lane * 4;
    int h    = blockIdx.x;
    int b    = blockIdx.y;

    const float4* wskT4 = (const float4*)g_wskT;
    const float4* f1T4  = (const float4*)g_f1T;
    const float4* f2T4  = (const float4*)g_f2T;

    // ---- stage x into h1s (coalesced) ----
    const float* xb = x + ((size_t)b*64*128 + h)*128;
    for (int i = tid; i < 2048; i += 256) {
        int c = i >> 5, w4 = (i & 31) * 4;
        *(float4*)&h1s[c*128 + w4] = *(const float4*)&xb[(size_t)c*16384 + w4];
    }
    // trig halves
    for (int i = tid; i < 1536; i += 256) {
        int ky = i >> 6, w = i & 63;
        tc[i] = g_cos[ky*128 + w];
        ts[i] = g_sin[ky*128 + w];
    }
    // S (pre-scaled, Si pre-negated) direct copy
    {
        size_t sb = ((size_t)b*128 + h) * 1536;
        for (int i = tid; i < 384; i += 256) {
            *(float4*)&SrT[i*4] = *(const float4*)&g_S_re[sb + (size_t)i*4];
            *(float4*)&SiT[i*4] = *(const float4*)&g_S_im[sb + (size_t)i*4];
        }
    }
    if (tid < 32) b1s[tid] = f1b_g[tid];
    if (tid < 64) { b2s[tid] = f2b_g[tid]; gs[tid] = gate_g[tid]; }
    __syncthreads();   // S1

    // ---- phase 1: skip (x from h1s, weights via uniform LDG) ----
    float2 acc[8][2];
    #pragma unroll
    for (int oo = 0; oo < 8; oo++) {
        acc[oo][0] = make_float2(0.f, 0.f);
        acc[oo][1] = make_float2(0.f, 0.f);
    }
    #pragma unroll 4
    for (int c = 0; c < 64; c++) {
        float4 xa = *(const float4*)&h1s[c*128 + w0];
        float2 xv0 = make_float2(xa.x, xa.y);
        float2 xv1 = make_float2(xa.z, xa.w);
        float4 wa = __ldg(&wskT4[(c*64 + o0) >> 2]);
        float4 wb = __ldg(&wskT4[(c*64 + o0 + 4) >> 2]);
        float wv[8] = { wa.x, wa.y, wa.z, wa.w, wb.x, wb.y, wb.z, wb.w };
        #pragma unroll
        for (int oo = 0; oo < 8; oo++) {
            float2 wd = dup2(wv[oo]);
            acc[oo][0] = ffma2(wd, xv0, acc[oo][0]);
            acc[oo][1] = ffma2(wd, xv1, acc[oo][1]);
        }
    }

    // ---- phase 2: spectral (inverse DFT over W, trig symmetry) ----
    int wq = w0 & 63;
    float signbase = (w0 >= 64) ? -1.0f : 1.0f;
    #pragma unroll 2
    for (int ky = 0; ky < 24; ky++) {
        float s = (ky & 1) ? signbase : 1.0f;
        float4 ca = *(const float4*)&tc[ky*64 + wq];
        float4 sa = *(const float4*)&ts[ky*64 + wq];
        float2 cv0 = make_float2(s*ca.x, s*ca.y);
        float2 cv1 = make_float2(s*ca.z, s*ca.w);
        float2 sv0 = make_float2(s*sa.x, s*sa.y);
        float2 sv1 = make_float2(s*sa.z, s*sa.w);
        float4 ra = *(const float4*)&SrT[ky*64 + o0];
        float4 rb = *(const float4*)&SrT[ky*64 + o0 + 4];
        float4 ia = *(const float4*)&SiT[ky*64 + o0];
        float4 ib = *(const float4*)&SiT[ky*64 + o0 + 4];
        float rv[8] = { ra.x, ra.y, ra.z, ra.w, rb.x, rb.y, rb.z, rb.w };
        float iv[8] = { ia.x, ia.y, ia.z, ia.w, ib.x, ib.y, ib.z, ib.w };
        #pragma unroll
        for (int oo = 0; oo < 8; oo++) {
            float2 rd = dup2(rv[oo]);
            float2 id = dup2(iv[oo]);
            acc[oo][0] = ffma2(rd, cv0, acc[oo][0]);
            acc[oo][0] = ffma2(id, sv0, acc[oo][0]);
            acc[oo][1] = ffma2(rd, cv1, acc[oo][1]);
            acc[oo][1] = ffma2(id, sv1, acc[oo][1]);
        }
    }

    // h1 = gelu(spec + skip)
    float h1v[8][4];
    #pragma unroll
    for (int oo = 0; oo < 8; oo++) {
        h1v[oo][0] = gelu_f(acc[oo][0].x);
        h1v[oo][1] = gelu_f(acc[oo][0].y);
        h1v[oo][2] = gelu_f(acc[oo][1].x);
        h1v[oo][3] = gelu_f(acc[oo][1].y);
    }
    __syncthreads();   // S2: x reads done -> safe to overwrite h1s
    #pragma unroll
    for (int oo = 0; oo < 8; oo++)
        *(float4*)&h1s[(o0+oo)*128 + w0] =
            make_float4(h1v[oo][0], h1v[oo][1], h1v[oo][2], h1v[oo][3]);
    __syncthreads();   // S3

    // ---- phase 3: fc1 + gelu -> zs ----
    int k0 = wid * 4;
    float2 acc2[4][2];
    #pragma unroll
    for (int kk = 0; kk < 4; kk++) {
        acc2[kk][0] = make_float2(0.f, 0.f);
        acc2[kk][1] = make_float2(0.f, 0.f);
    }
    #pragma unroll 4
    for (int c = 0; c < 64; c++) {
        float4 ha = *(const float4*)&h1s[c*128 + w0];
        float2 hv0 = make_float2(ha.x, ha.y);
        float2 hv1 = make_float2(ha.z, ha.w);
        float4 fv = __ldg(&f1T4[(c*32 + k0) >> 2]);
        float fw[4] = { fv.x, fv.y, fv.z, fv.w };
        #pragma unroll
        for (int kk = 0; kk < 4; kk++) {
            float2 fd = dup2(fw[kk]);
            acc2[kk][0] = ffma2(fd, hv0, acc2[kk][0]);
            acc2[kk][1] = ffma2(fd, hv1, acc2[kk][1]);
        }
    }
    #pragma unroll
    for (int kk = 0; kk < 4; kk++) {
        float bb = b1s[k0+kk];
        *(float4*)&zs[(k0+kk)*128 + w0] = make_float4(
            gelu_f(acc2[kk][0].x + bb), gelu_f(acc2[kk][0].y + bb),
            gelu_f(acc2[kk][1].x + bb), gelu_f(acc2[kk][1].y + bb));
    }
    __syncthreads();   // S4

    // ---- phase 4: fc2 + bias + gate*h1 ----
    float2 acc3[8][2];
    #pragma unroll
    for (int oo = 0; oo < 8; oo++) {
        float bb = b2s[o0+oo];
        acc3[oo][0] = make_float2(bb, bb);
        acc3[oo][1] = make_float2(bb, bb);
    }
    #pragma unroll 4
    for (int k = 0; k < 32; k++) {
        float4 za = *(const float4*)&zs[k*128 + w0];
        float2 zv0 = make_float2(za.x, za.y);
        float2 zv1 = make_float2(za.z, za.w);
        float4 fa = __ldg(&f2T4[(k*64 + o0) >> 2]);
        float4 fb = __ldg(&f2T4[(k*64 + o0 + 4) >> 2]);
        float fw[8] = { fa.x, fa.y, fa.z, fa.w, fb.x, fb.y, fb.z, fb.w };
        #pragma unroll
        for (int oo = 0; oo < 8; oo++) {
            float2 fd = dup2(fw[oo]);
            acc3[oo][0] = ffma2(fd, zv0, acc3[oo][0]);
            acc3[oo][1] = ffma2(fd, zv1, acc3[oo][1]);
        }
    }
    #pragma unroll
    for (int oo = 0; oo < 8; oo++) {
        float g = gs[o0+oo];
        float4 hh = *(const float4*)&h1s[(o0+oo)*128 + w0];
        float4 r = make_float4(acc3[oo][0].x + g*hh.x,
                               acc3[oo][0].y + g*hh.y,
                               acc3[oo][1].x + g*hh.z,
                               acc3[oo][1].y + g*hh.w);
        *(float4*)&out[(((size_t)b*64 + (o0+oo))*128 + h)*128 + w0] = r;
    }
}

// ---------------- launch ----------------
extern "C" void kernel_launch(void* const* d_in, const int* in_sizes, int n_in,
                              void* d_out, int out_size) {
    const float* x    = (const float*)d_in[0];
    const float* wre  = (const float*)d_in[1];
    const float* wim  = (const float*)d_in[2];
    const float* wsk  = (const float*)d_in[3];
    const float* f1w  = (const float*)d_in[4];
    const float* f1b  = (const float*)d_in[5];
    const float* f2w  = (const float*)d_in[6];
    const float* f2b  = (const float*)d_in[7];
    const float* gate = (const float*)d_in[8];
    float* out = (float*)d_out;

    cudaFuncSetAttribute(kA_dft, cudaFuncAttributeMaxDynamicSharedMemorySize,
                         KA_SMEM_FLOATS * (int)sizeof(float));
    cudaFuncSetAttribute(k5_final, cudaFuncAttributeMaxDynamicSharedMemorySize,
                         SMEM_K5_FLOATS * (int)sizeof(float));

    k0_init<<<16, 512>>>(wsk, f1w, f2w);
    kA_dft<<<1024, 384, KA_SMEM_FLOATS * sizeof(float)>>>(x);
    k3_mix<<<576, 512>>>(wre, wim);
    k4_idftH<<<512, 384>>>();
    dim3 g5(128, 16);
    k5_final<<<g5, 256, SMEM_K5_FLOATS * sizeof(float)>>>(
        x, f1b, f2b, gate, out);
}

// round 16
// speedup vs baseline: 2.1893x; 1.1195x over previous
#include <cuda_runtime.h>
#include <math.h>
#include <stdint.h>

#define Bn 16
#define Cn 64
#define Hn 128
#define Wn 128
#define MXn 24
#define MYn 24
#define HIDn 32

// ---------------- scratch (device globals; no runtime allocation) ----------
__device__ float g_xft_re[MXn*MYn*Bn*Cn];     // [(kx*24+ky)][b][c]
__device__ float g_xft_im[MXn*MYn*Bn*Cn];
__device__ float g_oftI[MXn*MYn*Bn*Cn*2];     // [m][b][o][re,im]
__device__ float g_S_re[Bn*Hn*MYn*Cn];        // [b][h][ky][o]  scaled
__device__ float g_S_im[Bn*Hn*MYn*Cn];        // [b][h][ky][o]  scaled, NEGATED
__device__ float g_cos[MYn*Wn];               // cos(pi*k*p/64)
__device__ float g_sin[MYn*Wn];
__device__ float g_twE[64*24];                // [w'][cf] even-ky family
__device__ float g_twO[64*24];                // [w'][cf] odd-ky family
__device__ float g_wskT[Cn*Cn];               // [c][o]
__device__ float g_f1T[Cn*HIDn];              // [c][k]
__device__ float g_f2T[HIDn*Cn];              // [k][o]

// ---------------- packed f32x2 helpers ----------------
__device__ __forceinline__ float2 ffma2(float2 a, float2 b, float2 c) {
    float2 r;
    asm("fma.rn.f32x2 %0, %1, %2, %3;"
        : "=l"(reinterpret_cast<unsigned long long&>(r))
        : "l"(reinterpret_cast<unsigned long long&>(a)),
          "l"(reinterpret_cast<unsigned long long&>(b)),
          "l"(reinterpret_cast<unsigned long long&>(c)));
    return r;
}
__device__ __forceinline__ float2 dup2(float x) { return make_float2(x, x); }

__device__ __forceinline__ float gelu_f(float v) {
    return 0.5f*v*(1.0f + erff(v*0.7071067811865476f));
}

// ---------------- K0: twiddles + parity tables + weight transposes --------
__global__ void k0_init(const float* __restrict__ wsk,
                        const float* __restrict__ f1w,
                        const float* __restrict__ f2w) {
    int tid = blockIdx.x*blockDim.x + threadIdx.x;
    int nt  = gridDim.x*blockDim.x;
    for (int i = tid; i < MYn*Wn; i += nt) {
        int k = i / Wn, w = i % Wn;
        float s, c;
        sincospif((float)(k*w) / 64.0f, &s, &c);
        g_cos[k*Wn + w] = c;
        g_sin[k*Wn + w] = s;
    }
    // parity-split W-DFT tables: [w'][cf], cf<12: cos(ky), cf>=12: -sin(ky)
    for (int i = tid; i < 2*64*24; i += nt) {
        int f = i / 1536, rem = i - f*1536;
        int wp = rem / 24, cf = rem - wp*24;
        int half = (cf < 12) ? cf : (cf - 12);
        int ky = 2*half + f;
        float s, c;
        sincospif((float)(ky*wp) / 64.0f, &s, &c);
        float v = (cf < 12) ? c : -s;
        if (f == 0) g_twE[wp*24 + cf] = v;
        else        g_twO[wp*24 + cf] = v;
    }
    for (int i = tid; i < 4096; i += nt) {
        int o = i >> 6, c = i & 63;
        g_wskT[c*64 + o] = wsk[i];
    }
    for (int i = tid; i < 2048; i += nt) {
        int k = i >> 6, c = i & 63;
        g_f1T[c*32 + k] = f1w[i];
    }
    for (int i = tid; i < 2048; i += nt) {
        int o = i >> 5, k = i & 31;
        g_f2T[k*64 + o] = f2w[i];
    }
}

// ---------------- kA: radix-2 fused DFT over W then H, per (b,c) ----------
// smem floats:
//   Xe  [32][132] 4224   (cs/sn alias here for H-stage: 24*64*2 = 3072)
//   Xo  [32][132] 4224
//   TwE [32][24]   768
//   TwO [32][24]   768
//   xwr [24][129] 3104
//   xwi [24][129] 3104
#define KA_OFF_XE   0
#define KA_OFF_XO   4224
#define KA_OFF_TWE  8448
#define KA_OFF_TWO  9216
#define KA_OFF_XWR  9984
#define KA_OFF_XWI  13088
#define KA_SMEM_FLOATS 16192

__global__ void __launch_bounds__(384, 3) kA_dft(const float* __restrict__ x) {
    extern __shared__ float sma[];
    float* Xe  = sma + KA_OFF_XE;
    float* Xo  = sma + KA_OFF_XO;
    float* TwE = sma + KA_OFF_TWE;
    float* TwO = sma + KA_OFF_TWO;
    float* xwr = sma + KA_OFF_XWR;
    float* xwi = sma + KA_OFF_XWI;
    float* cs  = sma + KA_OFF_XE;          // alias (H-stage)
    float* sn  = sma + KA_OFF_XE + 1536;   // alias

    int tid = threadIdx.x;
    int rg = tid & 31;
    int jg = tid >> 5;                     // 0..11
    int f  = (jg >= 6);                    // family: 0 even-ky, 1 odd-ky
    int jj = jg - 6*f;                     // 0..5
    int row0 = blockIdx.x * 128;

    float2 acc[2][4];                      // [row pair][col]
    #pragma unroll
    for (int i = 0; i < 2; i++)
        #pragma unroll
        for (int j = 0; j < 4; j++) acc[i][j] = make_float2(0.f, 0.f);

    const float* Xs = f ? Xo : Xe;

    for (int kt = 0; kt < 2; kt++) {
        // stage: Xe/Xo = x[w'] +/- x[w'+64], transposed
        for (int i = tid; i < 4096; i += 384) {
            int r = i >> 5, wl = i & 31;
            int wp = kt*32 + wl;
            float v1 = x[(size_t)(row0 + r)*128 + wp];
            float v2 = x[(size_t)(row0 + r)*128 + wp + 64];
            Xe[wl*132 + r] = v1 + v2;
            Xo[wl*132 + r] = v1 - v2;
        }
        for (int i = tid; i < 768; i += 384) {
            TwE[i] = g_twE[kt*768 + i];
            TwO[i] = g_twO[kt*768 + i];
        }
        __syncthreads();
        const float* Tw = f ? TwO : TwE;
        #pragma unroll
        for (int kk = 0; kk < 32; kk++) {
            float4 xa = *(const float4*)&Xs[kk*132 + 4*rg];
            float2 xp0 = make_float2(xa.x, xa.y);
            float2 xp1 = make_float2(xa.z, xa.w);
            float4 tq = *(const float4*)&Tw[kk*24 + 4*jj];
            float tv[4] = { tq.x, tq.y, tq.z, tq.w };
            #pragma unroll
            for (int j = 0; j < 4; j++) {
                float2 td = dup2(tv[j]);
                acc[0][j] = ffma2(xp0, td, acc[0][j]);
                acc[1][j] = ffma2(xp1, td, acc[1][j]);
            }
        }
        __syncthreads();
    }

    // store xw + load H-stage trig (into dead Xe alias)
    {
        #pragma unroll
        for (int j = 0; j < 4; j++) {
            int cf = 4*jj + j;
            float* dst;
            int ky;
            if (cf < 12) { dst = xwr; ky = 2*cf + f; }
            else         { dst = xwi; ky = 2*(cf - 12) + f; }
            #pragma unroll
            for (int i = 0; i < 4; i++) {
                int pair = i >> 1, half = i & 1;
                float v = half ? acc[pair][j].y : acc[pair][j].x;
                dst[ky*129 + 4*rg + i] = v;
            }
        }
    }
    __syncthreads();   // xw visible; Xe now dead -> reload as trig
    for (int i = tid; i < 1536; i += 384) {
        int kx = i >> 6, hp = i & 63;
        cs[i] = g_cos[kx*128 + hp];
        sn[i] = g_sin[kx*128 + hp];
    }
    __syncthreads();

    // H-stage: radix-2 over h
    if (tid < 288) {
        int ky  = tid % 24;
        int kxg = tid / 24;
        int kx0 = 2*kxg, kx1 = 2*kxg + 1;
        float2 acc0 = make_float2(0.f, 0.f);   // even kx
        float2 acc1 = make_float2(0.f, 0.f);   // odd kx
        #pragma unroll 4
        for (int hp = 0; hp < 64; hp++) {
            float a1 = xwr[ky*129 + hp];
            float a2 = xwr[ky*129 + hp + 64];
            float b1 = xwi[ky*129 + hp];
            float b2 = xwi[ky*129 + hp + 64];
            float ae = a1 + a2, ao = a1 - a2;
            float be = b1 + b2, bo = b1 - b2;
            float2 abe  = make_float2(ae, be);
            float2 bnae = make_float2(be, -ae);
            float2 abo  = make_float2(ao, bo);
            float2 bnao = make_float2(bo, -ao);
            acc0 = ffma2(abe,  dup2(cs[kx0*64 + hp]), acc0);
            acc0 = ffma2(bnae, dup2(sn[kx0*64 + hp]), acc0);
            acc1 = ffma2(abo,  dup2(cs[kx1*64 + hp]), acc1);
            acc1 = ffma2(bnao, dup2(sn[kx1*64 + hp]), acc1);
        }
        int b = blockIdx.x >> 6, c = blockIdx.x & 63;
        int m0 = kx0*24 + ky, m1 = kx1*24 + ky;
        g_xft_re[(m0*Bn + b)*Cn + c] = acc0.x;
        g_xft_im[(m0*Bn + b)*Cn + c] = acc0.y;
        g_xft_re[(m1*Bn + b)*Cn + c] = acc1.x;
        g_xft_im[(m1*Bn + b)*Cn + c] = acc1.y;
    }
}

// ---------------- K3: per-mode complex channel mix (512 thr) --------------
__global__ void __launch_bounds__(512) k3_mix(const float* __restrict__ wr_g,
                                              const float* __restrict__ wi_g) {
    __shared__ float xr_s[1024], xi_s[1024];
    __shared__ float wr_s[4096], wi_s[4096];
    int m = blockIdx.x, tid = threadIdx.x;
    if (tid < 256) {
        ((float4*)xr_s)[tid] = ((const float4*)g_xft_re)[m*256 + tid];
        ((float4*)xi_s)[tid] = ((const float4*)g_xft_im)[m*256 + tid];
    }
    for (int i = tid; i < 1024; i += 512) {
        ((float4*)wr_s)[i] = ((const float4*)wr_g)[(size_t)m*1024 + i];
        ((float4*)wi_s)[i] = ((const float4*)wi_g)[(size_t)m*1024 + i];
    }
    __syncthreads();

    int b  = tid >> 5;
    int og = tid & 31;
    float2 re = make_float2(0.f, 0.f), im = make_float2(0.f, 0.f);
    #pragma unroll 4
    for (int c = 0; c < 64; c++) {
        float xr = xr_s[b*64 + c];
        float xi = xi_s[b*64 + c];
        float2 wr = *(const float2*)&wr_s[c*64 + 2*og];
        float2 wi = *(const float2*)&wi_s[c*64 + 2*og];
        re = ffma2(dup2(xr),  wr, re);
        re = ffma2(dup2(-xi), wi, re);
        im = ffma2(dup2(xr),  wi, im);
        im = ffma2(dup2(xi),  wr, im);
    }
    size_t base = ((size_t)(m*Bn + b)*Cn + 2*og)*2;
    *(float4*)&g_oftI[base] = make_float4(re.x, im.x, re.y, im.y);
}

// ---------------- K4: inverse DFT over H, direct-L2 reads ----------------
__global__ void __launch_bounds__(384) k4_idftH() {
    __shared__ float tcs[24*4], tsn[24*4];

    int bx = blockIdx.x;
    int b  = bx >> 5;
    int h0 = (bx & 31) * 4;
    int tid = threadIdx.x;
    int o   = tid & 63;
    int ky0 = (tid >> 6) * 4;

    if (tid < 96) {
        int kx = tid >> 2, hh = tid & 3;
        tcs[kx*4 + hh] = g_cos[kx*128 + h0 + hh];
        tsn[kx*4 + hh] = g_sin[kx*128 + h0 + hh];
    }
    __syncthreads();

    float2 acc[4][4];
    #pragma unroll
    for (int hh = 0; hh < 4; hh++)
        #pragma unroll
        for (int j = 0; j < 4; j++) acc[hh][j] = make_float2(0.f, 0.f);

    #pragma unroll 2
    for (int kx = 0; kx < 24; kx++) {
        float2 v[4];
        size_t mb = ((size_t)((kx*24 + ky0)*Bn + b)*Cn + o)*2;
        #pragma unroll
        for (int j = 0; j < 4; j++)
            v[j] = *(const float2*)&g_oftI[mb + (size_t)j*(Bn*Cn*2)];
        float cr4[4], si4[4];
        #pragma unroll
        for (int hh = 0; hh < 4; hh++) {
            cr4[hh] = tcs[kx*4 + hh];
            si4[hh] = tsn[kx*4 + hh];
        }
        #pragma unroll
        for (int j = 0; j < 4; j++) {
            float2 red = dup2(v[j].x), imd = dup2(v[j].y);
            #pragma unroll
            for (int hh = 0; hh < 4; hh++) {
                float2 e1 = make_float2(cr4[hh], si4[hh]);
                float2 e2 = make_float2(-si4[hh], cr4[hh]);
                acc[hh][j] = ffma2(red, e1, acc[hh][j]);
                acc[hh][j] = ffma2(imd, e2, acc[hh][j]);
            }
        }
    }

    const float sc = 1.0f/16384.0f;
    #pragma unroll
    for (int hh = 0; hh < 4; hh++) {
        #pragma unroll
        for (int j = 0; j < 4; j++) {
            int ky = ky0 + j;
            float s = (ky == 0) ? sc : 2.0f*sc;
            size_t base = (((size_t)b*128 + h0 + hh)*24 + ky)*64 + o;
            g_S_re[base] =  s*acc[hh][j].x;
            g_S_im[base] = -s*acc[hh][j].y;
        }
    }
}

// ---------------- K5: 1-row GEMM, weights via uniform LDG, 3 CTAs/SM ------
#define OFF5_H1   0        // 8192   x stage -> h1
#define OFF5_ZS   8192     // 4096
#define OFF5_SR   12288    // 1536
#define OFF5_SI   13824    // 1536
#define OFF5_TC   15360    // 1536
#define OFF5_TS   16896    // 1536
#define OFF5_B1   18432    // 32
#define OFF5_B2   18464    // 64
#define OFF5_GS   18528    // 64
#define SMEM_K5_FLOATS 18592

__global__ void __launch_bounds__(256, 3) k5_final(
    const float* __restrict__ x,
    const float* __restrict__ f1b_g, const float* __restrict__ f2b_g,
    const float* __restrict__ gate_g,
    float* __restrict__ out)
{
    extern __shared__ float sm[];
    float* h1s  = sm + OFF5_H1;
    float* zs   = sm + OFF5_ZS;
    float* SrT  = sm + OFF5_SR;
    float* SiT  = sm + OFF5_SI;
    float* tc   = sm + OFF5_TC;
    float* ts   = sm + OFF5_TS;
    float* b1s  = sm + OFF5_B1;
    float* b2s  = sm + OFF5_B2;
    float* gs   = sm + OFF5_GS;

    int tid  = threadIdx.x;
    int lane = tid & 31;
    int wid  = tid >> 5;          // 0..7
    int o0   = wid * 8;
    int w0   = lane * 4;
    int h    = blockIdx.x;
    int b    = blockIdx.y;

    const float4* wskT4 = (const float4*)g_wskT;
    const float4* f1T4  = (const float4*)g_f1T;
    const float4* f2T4  = (const float4*)g_f2T;

    // ---- stage x into h1s (coalesced) ----
    const float* xb = x + ((size_t)b*64*128 + h)*128;
    for (int i = tid; i < 2048; i += 256) {
        int c = i >> 5, w4 = (i & 31) * 4;
        *(float4*)&h1s[c*128 + w4] = *(const float4*)&xb[(size_t)c*16384 + w4];
    }
    for (int i = tid; i < 1536; i += 256) {
        int ky = i >> 6, w = i & 63;
        tc[i] = g_cos[ky*128 + w];
        ts[i] = g_sin[ky*128 + w];
    }
    {
        size_t sb = ((size_t)b*128 + h) * 1536;
        for (int i = tid; i < 384; i += 256) {
            *(float4*)&SrT[i*4] = *(const float4*)&g_S_re[sb + (size_t)i*4];
            *(float4*)&SiT[i*4] = *(const float4*)&g_S_im[sb + (size_t)i*4];
        }
    }
    if (tid < 32) b1s[tid] = f1b_g[tid];
    if (tid < 64) { b2s[tid] = f2b_g[tid]; gs[tid] = gate_g[tid]; }
    __syncthreads();   // S1

    // ---- phase 1: skip ----
    float2 acc[8][2];
    #pragma unroll
    for (int oo = 0; oo < 8; oo++) {
        acc[oo][0] = make_float2(0.f, 0.f);
        acc[oo][1] = make_float2(0.f, 0.f);
    }
    #pragma unroll 4
    for (int c = 0; c < 64; c++) {
        float4 xa = *(const float4*)&h1s[c*128 + w0];
        float2 xv0 = make_float2(xa.x, xa.y);
        float2 xv1 = make_float2(xa.z, xa.w);
        float4 wa = __ldg(&wskT4[(c*64 + o0) >> 2]);
        float4 wb = __ldg(&wskT4[(c*64 + o0 + 4) >> 2]);
        float wv[8] = { wa.x, wa.y, wa.z, wa.w, wb.x, wb.y, wb.z, wb.w };
        #pragma unroll
        for (int oo = 0; oo < 8; oo++) {
            float2 wd = dup2(wv[oo]);
            acc[oo][0] = ffma2(wd, xv0, acc[oo][0]);
            acc[oo][1] = ffma2(wd, xv1, acc[oo][1]);
        }
    }

    // ---- phase 2: spectral ----
    int wq = w0 & 63;
    float signbase = (w0 >= 64) ? -1.0f : 1.0f;
    #pragma unroll 2
    for (int ky = 0; ky < 24; ky++) {
        float s = (ky & 1) ? signbase : 1.0f;
        float4 ca = *(const float4*)&tc[ky*64 + wq];
        float4 sa = *(const float4*)&ts[ky*64 + wq];
        float2 cv0 = make_float2(s*ca.x, s*ca.y);
        float2 cv1 = make_float2(s*ca.z, s*ca.w);
        float2 sv0 = make_float2(s*sa.x, s*sa.y);
        float2 sv1 = make_float2(s*sa.z, s*sa.w);
        float4 ra = *(const float4*)&SrT[ky*64 + o0];
        float4 rb = *(const float4*)&SrT[ky*64 + o0 + 4];
        float4 ia = *(const float4*)&SiT[ky*64 + o0];
        float4 ib = *(const float4*)&SiT[ky*64 + o0 + 4];
        float rv[8] = { ra.x, ra.y, ra.z, ra.w, rb.x, rb.y, rb.z, rb.w };
        float iv[8] = { ia.x, ia.y, ia.z, ia.w, ib.x, ib.y, ib.z, ib.w };
        #pragma unroll
        for (int oo = 0; oo < 8; oo++) {
            float2 rd = dup2(rv[oo]);
            float2 id = dup2(iv[oo]);
            acc[oo][0] = ffma2(rd, cv0, acc[oo][0]);
            acc[oo][0] = ffma2(id, sv0, acc[oo][0]);
            acc[oo][1] = ffma2(rd, cv1, acc[oo][1]);
            acc[oo][1] = ffma2(id, sv1, acc[oo][1]);
        }
    }

    // h1 = gelu(spec + skip)
    float h1v[8][4];
    #pragma unroll
    for (int oo = 0; oo < 8; oo++) {
        h1v[oo][0] = gelu_f(acc[oo][0].x);
        h1v[oo][1] = gelu_f(acc[oo][0].y);
        h1v[oo][2] = gelu_f(acc[oo][1].x);
        h1v[oo][3] = gelu_f(acc[oo][1].y);
    }
    __syncthreads();   // S2
    #pragma unroll
    for (int oo = 0; oo < 8; oo++)
        *(float4*)&h1s[(o0+oo)*128 + w0] =
            make_float4(h1v[oo][0], h1v[oo][1], h1v[oo][2], h1v[oo][3]);
    __syncthreads();   // S3

    // ---- phase 3: fc1 + gelu -> zs ----
    int k0 = wid * 4;
    float2 acc2[4][2];
    #pragma unroll
    for (int kk = 0; kk < 4; kk++) {
        acc2[kk][0] = make_float2(0.f, 0.f);
        acc2[kk][1] = make_float2(0.f, 0.f);
    }
    #pragma unroll 4
    for (int c = 0; c < 64; c++) {
        float4 ha = *(const float4*)&h1s[c*128 + w0];
        float2 hv0 = make_float2(ha.x, ha.y);
        float2 hv1 = make_float2(ha.z, ha.w);
        float4 fv = __ldg(&f1T4[(c*32 + k0) >> 2]);
        float fw[4] = { fv.x, fv.y, fv.z, fv.w };
        #pragma unroll
        for (int kk = 0; kk < 4; kk++) {
            float2 fd = dup2(fw[kk]);
            acc2[kk][0] = ffma2(fd, hv0, acc2[kk][0]);
            acc2[kk][1] = ffma2(fd, hv1, acc2[kk][1]);
        }
    }
    #pragma unroll
    for (int kk = 0; kk < 4; kk++) {
        float bb = b1s[k0+kk];
        *(float4*)&zs[(k0+kk)*128 + w0] = make_float4(
            gelu_f(acc2[kk][0].x + bb), gelu_f(acc2[kk][0].y + bb),
            gelu_f(acc2[kk][1].x + bb), gelu_f(acc2[kk][1].y + bb));
    }
    __syncthreads();   // S4

    // ---- phase 4: fc2 + bias + gate*h1 ----
    float2 acc3[8][2];
    #pragma unroll
    for (int oo = 0; oo < 8; oo++) {
        float bb = b2s[o0+oo];
        acc3[oo][0] = make_float2(bb, bb);
        acc3[oo][1] = make_float2(bb, bb);
    }
    #pragma unroll 4
    for (int k = 0; k < 32; k++) {
        float4 za = *(const float4*)&zs[k*128 + w0];
        float2 zv0 = make_float2(za.x, za.y);
        float2 zv1 = make_float2(za.z, za.w);
        float4 fa = __ldg(&f2T4[(k*64 + o0) >> 2]);
        float4 fb = __ldg(&f2T4[(k*64 + o0 + 4) >> 2]);
        float fw[8] = { fa.x, fa.y, fa.z, fa.w, fb.x, fb.y, fb.z, fb.w };
        #pragma unroll
        for (int oo = 0; oo < 8; oo++) {
            float2 fd = dup2(fw[oo]);
            acc3[oo][0] = ffma2(fd, zv0, acc3[oo][0]);
            acc3[oo][1] = ffma2(fd, zv1, acc3[oo][1]);
        }
    }
    #pragma unroll
    for (int oo = 0; oo < 8; oo++) {
        float g = gs[o0+oo];
        float4 hh = *(const float4*)&h1s[(o0+oo)*128 + w0];
        float4 r = make_float4(acc3[oo][0].x + g*hh.x,
                               acc3[oo][0].y + g*hh.y,
                               acc3[oo][1].x + g*hh.z,
                               acc3[oo][1].y + g*hh.w);
        *(float4*)&out[(((size_t)b*64 + (o0+oo))*128 + h)*128 + w0] = r;
    }
}

// ---------------- launch ----------------
extern "C" void kernel_launch(void* const* d_in, const int* in_sizes, int n_in,
                              void* d_out, int out_size) {
    const float* x    = (const float*)d_in[0];
    const float* wre  = (const float*)d_in[1];
    const float* wim  = (const float*)d_in[2];
    const float* wsk  = (const float*)d_in[3];
    const float* f1w  = (const float*)d_in[4];
    const float* f1b  = (const float*)d_in[5];
    const float* f2w  = (const float*)d_in[6];
    const float* f2b  = (const float*)d_in[7];
    const float* gate = (const float*)d_in[8];
    float* out = (float*)d_out;

    cudaFuncSetAttribute(kA_dft, cudaFuncAttributeMaxDynamicSharedMemorySize,
                         KA_SMEM_FLOATS * (int)sizeof(float));
    cudaFuncSetAttribute(k5_final, cudaFuncAttributeMaxDynamicSharedMemorySize,
                         SMEM_K5_FLOATS * (int)sizeof(float));

    k0_init<<<16, 512>>>(wsk, f1w, f2w);
    kA_dft<<<1024, 384, KA_SMEM_FLOATS * sizeof(float)>>>(x);
    k3_mix<<<576, 512>>>(wre, wim);
    k4_idftH<<<512, 384>>>();
    dim3 g5(128, 16);
    k5_final<<<g5, 256, SMEM_K5_FLOATS * sizeof(float)>>>(
        x, f1b, f2b, gate, out);
}

// round 17
// speedup vs baseline: 2.2097x; 1.0093x over previous
#include <cuda_runtime.h>
#include <math.h>
#include <stdint.h>

#define Bn 16
#define Cn 64
#define Hn 128
#define Wn 128
#define MXn 24
#define MYn 24
#define HIDn 32

// ---------------- scratch (device globals; no runtime allocation) ----------
__device__ float g_xft_re[MXn*MYn*Bn*Cn];     // [(kx*24+ky)][b][c]
__device__ float g_xft_im[MXn*MYn*Bn*Cn];
__device__ float g_oftI[MXn*MYn*Bn*Cn*2];     // [m][b][o][re,im]
__device__ float g_S_re[Bn*Hn*MYn*Cn];        // [b][h][ky][o]  scaled
__device__ float g_S_im[Bn*Hn*MYn*Cn];        // [b][h][ky][o]  scaled, NEGATED
__device__ float g_cos[MYn*Wn];               // cos(pi*k*p/64)
__device__ float g_sin[MYn*Wn];
__device__ float g_twE[64*24];                // [w'][cf] even-ky family
__device__ float g_twO[64*24];                // [w'][cf] odd-ky family
__device__ float g_wskT[Cn*Cn];               // [c][o]
__device__ float g_f1T[Cn*HIDn];              // [c][k]
__device__ float g_f2T[HIDn*Cn];              // [k][o]

// ---------------- packed f32x2 helpers ----------------
__device__ __forceinline__ float2 ffma2(float2 a, float2 b, float2 c) {
    float2 r;
    asm("fma.rn.f32x2 %0, %1, %2, %3;"
        : "=l"(reinterpret_cast<unsigned long long&>(r))
        : "l"(reinterpret_cast<unsigned long long&>(a)),
          "l"(reinterpret_cast<unsigned long long&>(b)),
          "l"(reinterpret_cast<unsigned long long&>(c)));
    return r;
}
__device__ __forceinline__ float2 fadd2(float2 a, float2 b) {
    float2 r;
    asm("add.rn.f32x2 %0, %1, %2;"
        : "=l"(reinterpret_cast<unsigned long long&>(r))
        : "l"(reinterpret_cast<unsigned long long&>(a)),
          "l"(reinterpret_cast<unsigned long long&>(b)));
    return r;
}
__device__ __forceinline__ float2 dup2(float x) { return make_float2(x, x); }

__device__ __forceinline__ float gelu_f(float v) {
    return 0.5f*v*(1.0f + erff(v*0.7071067811865476f));
}

// ---------------- K0: twiddles + parity tables + weight transposes --------
__global__ void k0_init(const float* __restrict__ wsk,
                        const float* __restrict__ f1w,
                        const float* __restrict__ f2w) {
    int tid = blockIdx.x*blockDim.x + threadIdx.x;
    int nt  = gridDim.x*blockDim.x;
    for (int i = tid; i < MYn*Wn; i += nt) {
        int k = i / Wn, w = i % Wn;
        float s, c;
        sincospif((float)(k*w) / 64.0f, &s, &c);
        g_cos[k*Wn + w] = c;
        g_sin[k*Wn + w] = s;
    }
    for (int i = tid; i < 2*64*24; i += nt) {
        int f = i / 1536, rem = i - f*1536;
        int wp = rem / 24, cf = rem - wp*24;
        int half = (cf < 12) ? cf : (cf - 12);
        int ky = 2*half + f;
        float s, c;
        sincospif((float)(ky*wp) / 64.0f, &s, &c);
        float v = (cf < 12) ? c : -s;
        if (f == 0) g_twE[wp*24 + cf] = v;
        else        g_twO[wp*24 + cf] = v;
    }
    for (int i = tid; i < 4096; i += nt) {
        int o = i >> 6, c = i & 63;
        g_wskT[c*64 + o] = wsk[i];
    }
    for (int i = tid; i < 2048; i += nt) {
        int k = i >> 6, c = i & 63;
        g_f1T[c*32 + k] = f1w[i];
    }
    for (int i = tid; i < 2048; i += nt) {
        int o = i >> 5, k = i & 31;
        g_f2T[k*64 + o] = f2w[i];
    }
}

// ---------------- kA: radix-2 fused DFT over W then H, per (b,c) ----------
#define KA_OFF_XE   0
#define KA_OFF_XO   4224
#define KA_OFF_TWE  8448
#define KA_OFF_TWO  9216
#define KA_OFF_XWR  9984
#define KA_OFF_XWI  13088
#define KA_SMEM_FLOATS 16192

__global__ void __launch_bounds__(384, 3) kA_dft(const float* __restrict__ x) {
    extern __shared__ float sma[];
    float* Xe  = sma + KA_OFF_XE;
    float* Xo  = sma + KA_OFF_XO;
    float* TwE = sma + KA_OFF_TWE;
    float* TwO = sma + KA_OFF_TWO;
    float* xwr = sma + KA_OFF_XWR;
    float* xwi = sma + KA_OFF_XWI;
    float* cs  = sma + KA_OFF_XE;          // alias (H-stage)
    float* sn  = sma + KA_OFF_XE + 1536;   // alias

    int tid = threadIdx.x;
    int rg = tid & 31;
    int jg = tid >> 5;
    int f  = (jg >= 6);
    int jj = jg - 6*f;
    int row0 = blockIdx.x * 128;

    float2 acc[2][4];
    #pragma unroll
    for (int i = 0; i < 2; i++)
        #pragma unroll
        for (int j = 0; j < 4; j++) acc[i][j] = make_float2(0.f, 0.f);

    const float* Xs = f ? Xo : Xe;

    for (int kt = 0; kt < 2; kt++) {
        for (int i = tid; i < 4096; i += 384) {
            int r = i >> 5, wl = i & 31;
            int wp = kt*32 + wl;
            float v1 = x[(size_t)(row0 + r)*128 + wp];
            float v2 = x[(size_t)(row0 + r)*128 + wp + 64];
            Xe[wl*132 + r] = v1 + v2;
            Xo[wl*132 + r] = v1 - v2;
        }
        for (int i = tid; i < 768; i += 384) {
            TwE[i] = g_twE[kt*768 + i];
            TwO[i] = g_twO[kt*768 + i];
        }
        __syncthreads();
        const float* Tw = f ? TwO : TwE;
        #pragma unroll
        for (int kk = 0; kk < 32; kk++) {
            float4 xa = *(const float4*)&Xs[kk*132 + 4*rg];
            float2 xp0 = make_float2(xa.x, xa.y);
            float2 xp1 = make_float2(xa.z, xa.w);
            float4 tq = *(const float4*)&Tw[kk*24 + 4*jj];
            float tv[4] = { tq.x, tq.y, tq.z, tq.w };
            #pragma unroll
            for (int j = 0; j < 4; j++) {
                float2 td = dup2(tv[j]);
                acc[0][j] = ffma2(xp0, td, acc[0][j]);
                acc[1][j] = ffma2(xp1, td, acc[1][j]);
            }
        }
        __syncthreads();
    }

    {
        #pragma unroll
        for (int j = 0; j < 4; j++) {
            int cf = 4*jj + j;
            float* dst;
            int ky;
            if (cf < 12) { dst = xwr; ky = 2*cf + f; }
            else         { dst = xwi; ky = 2*(cf - 12) + f; }
            #pragma unroll
            for (int i = 0; i < 4; i++) {
                int pair = i >> 1, half = i & 1;
                float v = half ? acc[pair][j].y : acc[pair][j].x;
                dst[ky*129 + 4*rg + i] = v;
            }
        }
    }
    __syncthreads();
    for (int i = tid; i < 1536; i += 384) {
        int kx = i >> 6, hp = i & 63;
        cs[i] = g_cos[kx*128 + hp];
        sn[i] = g_sin[kx*128 + hp];
    }
    __syncthreads();

    if (tid < 288) {
        int ky  = tid % 24;
        int kxg = tid / 24;
        int kx0 = 2*kxg, kx1 = 2*kxg + 1;
        float2 acc0 = make_float2(0.f, 0.f);
        float2 acc1 = make_float2(0.f, 0.f);
        #pragma unroll 4
        for (int hp = 0; hp < 64; hp++) {
            float a1 = xwr[ky*129 + hp];
            float a2 = xwr[ky*129 + hp + 64];
            float b1 = xwi[ky*129 + hp];
            float b2 = xwi[ky*129 + hp + 64];
            float ae = a1 + a2, ao = a1 - a2;
            float be = b1 + b2, bo = b1 - b2;
            float2 abe  = make_float2(ae, be);
            float2 bnae = make_float2(be, -ae);
            float2 abo  = make_float2(ao, bo);
            float2 bnao = make_float2(bo, -ao);
            acc0 = ffma2(abe,  dup2(cs[kx0*64 + hp]), acc0);
            acc0 = ffma2(bnae, dup2(sn[kx0*64 + hp]), acc0);
            acc1 = ffma2(abo,  dup2(cs[kx1*64 + hp]), acc1);
            acc1 = ffma2(bnao, dup2(sn[kx1*64 + hp]), acc1);
        }
        int b = blockIdx.x >> 6, c = blockIdx.x & 63;
        int m0 = kx0*24 + ky, m1 = kx1*24 + ky;
        g_xft_re[(m0*Bn + b)*Cn + c] = acc0.x;
        g_xft_im[(m0*Bn + b)*Cn + c] = acc0.y;
        g_xft_re[(m1*Bn + b)*Cn + c] = acc1.x;
        g_xft_im[(m1*Bn + b)*Cn + c] = acc1.y;
    }
}

// ---------------- K3: per-mode complex channel mix (512 thr) --------------
__global__ void __launch_bounds__(512) k3_mix(const float* __restrict__ wr_g,
                                              const float* __restrict__ wi_g) {
    __shared__ float xr_s[1024], xi_s[1024];
    __shared__ float wr_s[4096], wi_s[4096];
    int m = blockIdx.x, tid = threadIdx.x;
    if (tid < 256) {
        ((float4*)xr_s)[tid] = ((const float4*)g_xft_re)[m*256 + tid];
        ((float4*)xi_s)[tid] = ((const float4*)g_xft_im)[m*256 + tid];
    }
    for (int i = tid; i < 1024; i += 512) {
        ((float4*)wr_s)[i] = ((const float4*)wr_g)[(size_t)m*1024 + i];
        ((float4*)wi_s)[i] = ((const float4*)wi_g)[(size_t)m*1024 + i];
    }
    __syncthreads();

    int b  = tid >> 5;
    int og = tid & 31;
    float2 re = make_float2(0.f, 0.f), im = make_float2(0.f, 0.f);
    #pragma unroll 4
    for (int c = 0; c < 64; c++) {
        float xr = xr_s[b*64 + c];
        float xi = xi_s[b*64 + c];
        float2 wr = *(const float2*)&wr_s[c*64 + 2*og];
        float2 wi = *(const float2*)&wi_s[c*64 + 2*og];
        re = ffma2(dup2(xr),  wr, re);
        re = ffma2(dup2(-xi), wi, re);
        im = ffma2(dup2(xr),  wi, im);
        im = ffma2(dup2(xi),  wr, im);
    }
    size_t base = ((size_t)(m*Bn + b)*Cn + 2*og)*2;
    *(float4*)&g_oftI[base] = make_float4(re.x, im.x, re.y, im.y);
}

// ---------------- K4: inverse DFT over H, pointer-incremented L2 reads ----
__global__ void __launch_bounds__(384) k4_idftH() {
    __shared__ float tcs[24*4], tsn[24*4];

    int bx = blockIdx.x;
    int b  = bx >> 5;
    int h0 = (bx & 31) * 4;
    int tid = threadIdx.x;
    int o   = tid & 63;
    int ky0 = (tid >> 6) * 4;

    if (tid < 96) {
        int kx = tid >> 2, hh = tid & 3;
        tcs[kx*4 + hh] = g_cos[kx*128 + h0 + hh];
        tsn[kx*4 + hh] = g_sin[kx*128 + h0 + hh];
    }
    __syncthreads();

    float2 acc[4][4];
    #pragma unroll
    for (int hh = 0; hh < 4; hh++)
        #pragma unroll
        for (int j = 0; j < 4; j++) acc[hh][j] = make_float2(0.f, 0.f);

    const float* po = g_oftI + ((size_t)(ky0*Bn + b)*Cn + o)*2;
    const int stepJ  = Bn*Cn*2;        // 2048 floats per ky
    const int stepKX = 24*stepJ;       // per kx
    #pragma unroll 4
    for (int kx = 0; kx < 24; kx++) {
        float4 cq = *(const float4*)&tcs[kx*4];
        float4 sq = *(const float4*)&tsn[kx*4];
        float2 v[4];
        v[0] = *(const float2*)(po);
        v[1] = *(const float2*)(po + stepJ);
        v[2] = *(const float2*)(po + 2*stepJ);
        v[3] = *(const float2*)(po + 3*stepJ);
        po += stepKX;
        float cr4[4] = { cq.x, cq.y, cq.z, cq.w };
        float si4[4] = { sq.x, sq.y, sq.z, sq.w };
        #pragma unroll
        for (int j = 0; j < 4; j++) {
            float2 red = dup2(v[j].x), imd = dup2(v[j].y);
            #pragma unroll
            for (int hh = 0; hh < 4; hh++) {
                float2 e1 = make_float2(cr4[hh], si4[hh]);
                float2 e2 = make_float2(-si4[hh], cr4[hh]);
                acc[hh][j] = ffma2(red, e1, acc[hh][j]);
                acc[hh][j] = ffma2(imd, e2, acc[hh][j]);
            }
        }
    }

    const float sc = 1.0f/16384.0f;
    #pragma unroll
    for (int hh = 0; hh < 4; hh++) {
        #pragma unroll
        for (int j = 0; j < 4; j++) {
            int ky = ky0 + j;
            float s = (ky == 0) ? sc : 2.0f*sc;
            size_t base = (((size_t)b*128 + h0 + hh)*24 + ky)*64 + o;
            g_S_re[base] =  s*acc[hh][j].x;
            g_S_im[base] = -s*acc[hh][j].y;
        }
    }
}

// ---------------- K5: 1-row GEMM, ky-parity split spectral, 3 CTAs/SM -----
#define OFF5_H1   0        // 8192
#define OFF5_ZS   8192     // 4096
#define OFF5_SR   12288    // 1536
#define OFF5_SI   13824    // 1536
#define OFF5_TC   15360    // 1536
#define OFF5_TS   16896    // 1536
#define OFF5_B1   18432    // 32
#define OFF5_B2   18464    // 64
#define OFF5_GS   18528    // 64
#define SMEM_K5_FLOATS 18592

__global__ void __launch_bounds__(256, 3) k5_final(
    const float* __restrict__ x,
    const float* __restrict__ f1b_g, const float* __restrict__ f2b_g,
    const float* __restrict__ gate_g,
    float* __restrict__ out)
{
    extern __shared__ float sm[];
    float* h1s  = sm + OFF5_H1;
    float* zs   = sm + OFF5_ZS;
    float* SrT  = sm + OFF5_SR;
    float* SiT  = sm + OFF5_SI;
    float* tc   = sm + OFF5_TC;
    float* ts   = sm + OFF5_TS;
    float* b1s  = sm + OFF5_B1;
    float* b2s  = sm + OFF5_B2;
    float* gs   = sm + OFF5_GS;

    int tid  = threadIdx.x;
    int lane = tid & 31;
    int wid  = tid >> 5;          // 0..7
    int o0   = wid * 8;
    int w2   = lane * 2;          // w' in [0,64); pixels: w', w'+1, w'+64, w'+65
    int h    = blockIdx.x;
    int b    = blockIdx.y;

    const float4* wskT4 = (const float4*)g_wskT;
    const float4* f1T4  = (const float4*)g_f1T;
    const float4* f2T4  = (const float4*)g_f2T;

    // ---- stage x into h1s (coalesced) ----
    const float* xb = x + ((size_t)b*64*128 + h)*128;
    for (int i = tid; i < 2048; i += 256) {
        int c = i >> 5, w4 = (i & 31) * 4;
        *(float4*)&h1s[c*128 + w4] = *(const float4*)&xb[(size_t)c*16384 + w4];
    }
    for (int i = tid; i < 1536; i += 256) {
        int ky = i >> 6, w = i & 63;
        tc[i] = g_cos[ky*128 + w];
        ts[i] = g_sin[ky*128 + w];
    }
    {
        size_t sb = ((size_t)b*128 + h) * 1536;
        for (int i = tid; i < 384; i += 256) {
            *(float4*)&SrT[i*4] = *(const float4*)&g_S_re[sb + (size_t)i*4];
            *(float4*)&SiT[i*4] = *(const float4*)&g_S_im[sb + (size_t)i*4];
        }
    }
    if (tid < 32) b1s[tid] = f1b_g[tid];
    if (tid < 64) { b2s[tid] = f2b_g[tid]; gs[tid] = gate_g[tid]; }
    __syncthreads();   // S1

    // ---- phase 1: skip ----
    float2 acc[8][2];   // [oo][0]=low half (w',w'+1), [1]=high (w'+64,w'+65)
    #pragma unroll
    for (int oo = 0; oo < 8; oo++) {
        acc[oo][0] = make_float2(0.f, 0.f);
        acc[oo][1] = make_float2(0.f, 0.f);
    }
    #pragma unroll 4
    for (int c = 0; c < 64; c++) {
        float2 xlo = *(const float2*)&h1s[c*128 + w2];
        float2 xhi = *(const float2*)&h1s[c*128 + w2 + 64];
        float4 wa = __ldg(&wskT4[(c*64 + o0) >> 2]);
        float4 wb = __ldg(&wskT4[(c*64 + o0 + 4) >> 2]);
        float wv[8] = { wa.x, wa.y, wa.z, wa.w, wb.x, wb.y, wb.z, wb.w };
        #pragma unroll
        for (int oo = 0; oo < 8; oo++) {
            float2 wd = dup2(wv[oo]);
            acc[oo][0] = ffma2(wd, xlo, acc[oo][0]);
            acc[oo][1] = ffma2(wd, xhi, acc[oo][1]);
        }
    }

    // ---- phase 2: spectral via ky-parity split (E/O) ----
    #pragma unroll
    for (int g = 0; g < 2; g++) {
        int og4 = o0 + 4*g;
        float2 aE[4], aO[4];
        #pragma unroll
        for (int j = 0; j < 4; j++) {
            aE[j] = make_float2(0.f, 0.f);
            aO[j] = make_float2(0.f, 0.f);
        }
        // even ky
        #pragma unroll 2
        for (int kp = 0; kp < 12; kp++) {
            int ky = 2*kp;
            float2 cv = *(const float2*)&tc[ky*64 + w2];
            float2 sv = *(const float2*)&ts[ky*64 + w2];
            float4 ra = *(const float4*)&SrT[ky*64 + og4];
            float4 ia = *(const float4*)&SiT[ky*64 + og4];
            float rv[4] = { ra.x, ra.y, ra.z, ra.w };
            float iv[4] = { ia.x, ia.y, ia.z, ia.w };
            #pragma unroll
            for (int j = 0; j < 4; j++) {
                aE[j] = ffma2(dup2(rv[j]), cv, aE[j]);
                aE[j] = ffma2(dup2(iv[j]), sv, aE[j]);
            }
        }
        // odd ky
        #pragma unroll 2
        for (int kp = 0; kp < 12; kp++) {
            int ky = 2*kp + 1;
            float2 cv = *(const float2*)&tc[ky*64 + w2];
            float2 sv = *(const float2*)&ts[ky*64 + w2];
            float4 ra = *(const float4*)&SrT[ky*64 + og4];
            float4 ia = *(const float4*)&SiT[ky*64 + og4];
            float rv[4] = { ra.x, ra.y, ra.z, ra.w };
            float iv[4] = { ia.x, ia.y, ia.z, ia.w };
            #pragma unroll
            for (int j = 0; j < 4; j++) {
                aO[j] = ffma2(dup2(rv[j]), cv, aO[j]);
                aO[j] = ffma2(dup2(iv[j]), sv, aO[j]);
            }
        }
        // combine: low += E+O, high += E-O
        #pragma unroll
        for (int j = 0; j < 4; j++) {
            int oo = 4*g + j;
            float2 s = fadd2(aE[j], aO[j]);
            float2 d = ffma2(dup2(-2.0f), aO[j], s);   // E - O
            acc[oo][0] = fadd2(acc[oo][0], s);
            acc[oo][1] = fadd2(acc[oo][1], d);
        }
    }

    // h1 = gelu(spec + skip)
    float h1v[8][4];
    #pragma unroll
    for (int oo = 0; oo < 8; oo++) {
        h1v[oo][0] = gelu_f(acc[oo][0].x);
        h1v[oo][1] = gelu_f(acc[oo][0].y);
        h1v[oo][2] = gelu_f(acc[oo][1].x);
        h1v[oo][3] = gelu_f(acc[oo][1].y);
    }
    __syncthreads();   // S2: x reads done -> safe to overwrite h1s
    #pragma unroll
    for (int oo = 0; oo < 8; oo++) {
        *(float2*)&h1s[(o0+oo)*128 + w2]      = make_float2(h1v[oo][0], h1v[oo][1]);
        *(float2*)&h1s[(o0+oo)*128 + w2 + 64] = make_float2(h1v[oo][2], h1v[oo][3]);
    }
    __syncthreads();   // S3

    // ---- phase 3: fc1 + gelu -> zs ----
    int k0 = wid * 4;
    float2 acc2[4][2];
    #pragma unroll
    for (int kk = 0; kk < 4; kk++) {
        acc2[kk][0] = make_float2(0.f, 0.f);
        acc2[kk][1] = make_float2(0.f, 0.f);
    }
    #pragma unroll 4
    for (int c = 0; c < 64; c++) {
        float2 hlo = *(const float2*)&h1s[c*128 + w2];
        float2 hhi = *(const float2*)&h1s[c*128 + w2 + 64];
        float4 fv = __ldg(&f1T4[(c*32 + k0) >> 2]);
        float fw[4] = { fv.x, fv.y, fv.z, fv.w };
        #pragma unroll
        for (int kk = 0; kk < 4; kk++) {
            float2 fd = dup2(fw[kk]);
            acc2[kk][0] = ffma2(fd, hlo, acc2[kk][0]);
            acc2[kk][1] = ffma2(fd, hhi, acc2[kk][1]);
        }
    }
    #pragma unroll
    for (int kk = 0; kk < 4; kk++) {
        float bb = b1s[k0+kk];
        *(float2*)&zs[(k0+kk)*128 + w2] = make_float2(
            gelu_f(acc2[kk][0].x + bb), gelu_f(acc2[kk][0].y + bb));
        *(float2*)&zs[(k0+kk)*128 + w2 + 64] = make_float2(
            gelu_f(acc2[kk][1].x + bb), gelu_f(acc2[kk][1].y + bb));
    }
    __syncthreads();   // S4

    // ---- phase 4: fc2 + bias + gate*h1 ----
    float2 acc3[8][2];
    #pragma unroll
    for (int oo = 0; oo < 8; oo++) {
        float bb = b2s[o0+oo];
        acc3[oo][0] = make_float2(bb, bb);
        acc3[oo][1] = make_float2(bb, bb);
    }
    #pragma unroll 4
    for (int k = 0; k < 32; k++) {
        float2 zlo = *(const float2*)&zs[k*128 + w2];
        float2 zhi = *(const float2*)&zs[k*128 + w2 + 64];
        float4 fa = __ldg(&f2T4[(k*64 + o0) >> 2]);
        float4 fb = __ldg(&f2T4[(k*64 + o0 + 4) >> 2]);
        float fw[8] = { fa.x, fa.y, fa.z, fa.w, fb.x, fb.y, fb.z, fb.w };
        #pragma unroll
        for (int oo = 0; oo < 8; oo++) {
            float2 fd = dup2(fw[oo]);
            acc3[oo][0] = ffma2(fd, zlo, acc3[oo][0]);
            acc3[oo][1] = ffma2(fd, zhi, acc3[oo][1]);
        }
    }
    #pragma unroll
    for (int oo = 0; oo < 8; oo++) {
        float g = gs[o0+oo];
        float2 hlo = *(const float2*)&h1s[(o0+oo)*128 + w2];
        float2 hhi = *(const float2*)&h1s[(o0+oo)*128 + w2 + 64];
        float* dst = &out[(((size_t)b*64 + (o0+oo))*128 + h)*128];
        *(float2*)&dst[w2] = make_float2(acc3[oo][0].x + g*hlo.x,
                                         acc3[oo][0].y + g*hlo.y);
        *(float2*)&dst[w2 + 64] = make_float2(acc3[oo][1].x + g*hhi.x,
                                              acc3[oo][1].y + g*hhi.y);
    }
}

// ---------------- launch ----------------
extern "C" void kernel_launch(void* const* d_in, const int* in_sizes, int n_in,
                              void* d_out, int out_size) {
    const float* x    = (const float*)d_in[0];
    const float* wre  = (const float*)d_in[1];
    const float* wim  = (const float*)d_in[2];
    const float* wsk  = (const float*)d_in[3];
    const float* f1w  = (const float*)d_in[4];
    const float* f1b  = (const float*)d_in[5];
    const float* f2w  = (const float*)d_in[6];
    const float* f2b  = (const float*)d_in[7];
    const float* gate = (const float*)d_in[8];
    float* out = (float*)d_out;

    cudaFuncSetAttribute(kA_dft, cudaFuncAttributeMaxDynamicSharedMemorySize,
                         KA_SMEM_FLOATS * (int)sizeof(float));
    cudaFuncSetAttribute(k5_final, cudaFuncAttributeMaxDynamicSharedMemorySize,
                         SMEM_K5_FLOATS * (int)sizeof(float));

    k0_init<<<16, 512>>>(wsk, f1w, f2w);
    kA_dft<<<1024, 384, KA_SMEM_FLOATS * sizeof(float)>>>(x);
    k3_mix<<<576, 512>>>(wre, wim);
    k4_idftH<<<512, 384>>>();
    dim3 g5(128, 16);
    k5_final<<<g5, 256, SMEM_K5_FLOATS * sizeof(float)>>>(
        x, f1b, f2b, gate, out);
}